// round 8
// baseline (speedup 1.0000x reference)
#include <cuda_runtime.h>
#include <cuda_bf16.h>
#include <cstdint>
#include <math.h>

// Problem constants
#define CB   16
#define CT   2048
#define CC   512
#define CH   4
#define CDH  128
#define NTOK (CB * CT)     // 32768 tokens
#define NROW (NTOK * 2)    // 65536 token-device rows

// GEMM tiling: 128x256 tile, BK=64, 512 threads (16 warps, 2x8)
#define BM 128
#define BN 256
#define BK 64
#define STAGE_BYTES 98304          // Ah 16K | Al 16K | Bh 32K | Bl 32K
#define SMEM_TOTAL  196608         // 2 stages
#define EPI_STRIDE  257

#define SW128(off) ((off) ^ (((off) >> 3) & 0x70))

// ---------------------------------------------------------------------------
// Scratch (static __device__; no runtime allocation)
// ---------------------------------------------------------------------------
__device__ __nv_bfloat16 g_XEh [(size_t)NROW * CC];
__device__ __nv_bfloat16 g_XEl [(size_t)NROW * CC];
__device__ float         g_QKV [(size_t)NROW * 3 * CC];
__device__ __nv_bfloat16 g_CTXh[(size_t)NROW * CC];   // viewed as (NTOK, 1024)
__device__ __nv_bfloat16 g_CTXl[(size_t)NROW * CC];
__device__ float         g_PATT[(size_t)NTOK * 4];
__device__ __nv_bfloat16 g_W1h[3 * CC * CC], g_W1l[3 * CC * CC];
// fused-weight pipeline
__device__ float         g_PART[8 * CC * CC];         // split-K partials (8 MB)
__device__ float         g_S1[CC * CC];               // Wp @ Wo
__device__ float         g_S2[CC * CC];               // Wi @ Wo
__device__ float         g_U [CC * 2 * CC];           // [W2a@S1 | W2b@S2] (512, 1024)
__device__ __nv_bfloat16 g_Uh[CC * 2 * CC], g_Ul[CC * 2 * CC];
__device__ float         g_BB[2 * CC];                // Wp@bo+bp, Wi@bo+bi
__device__ float         g_BT[CC];                    // combined output bias

// ---------------------------------------------------------------------------
// Helpers
// ---------------------------------------------------------------------------
__device__ __forceinline__ uint32_t smem_u32(const void* p) {
    uint32_t a;
    asm("{ .reg .u64 t; cvta.to.shared.u64 t, %1; cvt.u32.u64 %0, t; }" : "=r"(a) : "l"(p));
    return a;
}
__device__ __forceinline__ void cp16(uint32_t dst, const void* src) {
    unsigned long long g = (unsigned long long)__cvta_generic_to_global(src);
    asm volatile("cp.async.cg.shared.global [%0], [%1], 16;" :: "r"(dst), "l"(g) : "memory");
}
__device__ __forceinline__ void cp_commit() { asm volatile("cp.async.commit_group;" ::: "memory"); }
__device__ __forceinline__ void cp_wait1()  { asm volatile("cp.async.wait_group 1;" ::: "memory"); }
__device__ __forceinline__ void cp_wait0()  { asm volatile("cp.async.wait_group 0;" ::: "memory"); }

__device__ __forceinline__ void ldsm4(uint32_t* r, uint32_t addr) {
    asm volatile("ldmatrix.sync.aligned.m8n8.x4.shared.b16 {%0,%1,%2,%3}, [%4];"
                 : "=r"(r[0]), "=r"(r[1]), "=r"(r[2]), "=r"(r[3]) : "r"(addr));
}
__device__ __forceinline__ void mma16816(float* d, const uint32_t* a, const uint32_t* b) {
    asm volatile(
        "mma.sync.aligned.m16n8k16.row.col.f32.bf16.bf16.f32 "
        "{%0,%1,%2,%3}, {%4,%5,%6,%7}, {%8,%9}, {%0,%1,%2,%3};"
        : "+f"(d[0]), "+f"(d[1]), "+f"(d[2]), "+f"(d[3])
        : "r"(a[0]), "r"(a[1]), "r"(a[2]), "r"(a[3]), "r"(b[0]), "r"(b[1]));
}
__device__ __forceinline__ void split2(float v, __nv_bfloat16& h, __nv_bfloat16& l) {
    h = __float2bfloat16(v);
    l = __float2bfloat16(v - __bfloat162float(h));
}

// ---------------------------------------------------------------------------
// K0: fp32 -> hi/lo bf16
// ---------------------------------------------------------------------------
__global__ void k_cvt(const float* __restrict__ s, __nv_bfloat16* __restrict__ h,
                      __nv_bfloat16* __restrict__ l, int n) {
    int i = blockIdx.x * 256 + threadIdx.x;
    if (i < n) split2(s[i], h[i], l[i]);
}

// ---------------------------------------------------------------------------
// Split-K fp32 SGEMM (C = A @ B), 64x64 tile, 8 K-slices of 64.
// Shared rows padded to 68 floats (16B multiple) - LDS.128 alignment.
// ---------------------------------------------------------------------------
__global__ void __launch_bounds__(256)
k_snn(const float* __restrict__ A, int lda, const float* __restrict__ B, int ldb) {
    __shared__ __align__(16) float As[64][68];   // [k][m]
    __shared__ __align__(16) float Bs[64][68];   // [k][n]
    int tid = threadIdx.x;
    int n0 = blockIdx.x * 64, m0 = blockIdx.y * 64;
    int k0 = blockIdx.z * 64;
    int tr = tid / 16, tc = tid % 16;
    int lr = tid / 16, lc4 = (tid % 16) * 4;

    #pragma unroll
    for (int h = 0; h < 4; h++) {
        int r = lr + h * 16;
        float4 a = *(const float4*)(A + (size_t)(m0 + r) * lda + k0 + lc4);
        As[lc4 + 0][r] = a.x; As[lc4 + 1][r] = a.y;
        As[lc4 + 2][r] = a.z; As[lc4 + 3][r] = a.w;
        *(float4*)&Bs[r][lc4] = *(const float4*)(B + (size_t)(k0 + r) * ldb + n0 + lc4);
    }
    __syncthreads();

    float acc[4][4];
    #pragma unroll
    for (int i = 0; i < 4; i++)
        #pragma unroll
        for (int j = 0; j < 4; j++) acc[i][j] = 0.f;

    #pragma unroll 8
    for (int k = 0; k < 64; k++) {
        float4 ra = *(const float4*)&As[k][tr * 4];
        float4 rb = *(const float4*)&Bs[k][tc * 4];
        float a[4] = {ra.x, ra.y, ra.z, ra.w};
        float b[4] = {rb.x, rb.y, rb.z, rb.w};
        #pragma unroll
        for (int i = 0; i < 4; i++)
            #pragma unroll
            for (int j = 0; j < 4; j++)
                acc[i][j] += a[i] * b[j];
    }

    float* part = g_PART + (size_t)blockIdx.z * CC * CC;
    #pragma unroll
    for (int i = 0; i < 4; i++)
        *(float4*)(part + (size_t)(m0 + tr * 4 + i) * CC + n0 + tc * 4) =
            make_float4(acc[i][0], acc[i][1], acc[i][2], acc[i][3]);
}

// reduce 8 partials into dst (fixed order -> deterministic)
__global__ void __launch_bounds__(256)
k_sred(float* __restrict__ dst, int ldc) {
    int m = blockIdx.x;
    int n = threadIdx.x * 2;
    #pragma unroll
    for (int q = 0; q < 2; q++) {
        float s = 0.f;
        #pragma unroll
        for (int sl = 0; sl < 8; sl++)
            s += g_PART[(size_t)sl * CC * CC + (size_t)m * CC + n + q];
        dst[(size_t)m * ldc + n + q] = s;
    }
}

// ---------------------------------------------------------------------------
// Bias folding
// ---------------------------------------------------------------------------
__global__ void k_bias1(const float* __restrict__ wp, const float* __restrict__ bp,
                        const float* __restrict__ wi, const float* __restrict__ bi,
                        const float* __restrict__ bo) {
    int i = threadIdx.x + blockIdx.x * 128;
    float s0 = bp[i], s1 = bi[i];
    for (int k = 0; k < CC; k++) {
        float b = bo[k];
        s0 += wp[i * CC + k] * b;
        s1 += wi[i * CC + k] * b;
    }
    g_BB[i] = s0;
    g_BB[CC + i] = s1;
}
__global__ void k_bias2(const float* __restrict__ w2, const float* __restrict__ b2) {
    int n = threadIdx.x + blockIdx.x * 128;
    float s = b2[n];
    for (int a = 0; a < CC; a++)
        s += w2[n * 2 * CC + a] * g_BB[a] + w2[n * 2 * CC + CC + a] * g_BB[CC + a];
    g_BT[n] = s;
}

// ---------------------------------------------------------------------------
// K1: x (B, C, 2, T) -> XE hi/lo with device embedding
// ---------------------------------------------------------------------------
__global__ void k_embed(const float* __restrict__ x, const float* __restrict__ emb) {
    __shared__ float s[32][33];
    int t0 = blockIdx.x * 32;
    int c0 = blockIdx.y * 32;
    int bd = blockIdx.z;
    int b = bd >> 1, d = bd & 1;

    #pragma unroll
    for (int j = 0; j < 4; j++) {
        int c = c0 + threadIdx.y + j * 8;
        s[threadIdx.y + j * 8][threadIdx.x] =
            x[(((size_t)b * CC + c) * 2 + d) * CT + t0 + threadIdx.x];
    }
    __syncthreads();
    #pragma unroll
    for (int j = 0; j < 4; j++) {
        int t = t0 + threadIdx.y + j * 8;
        int c = c0 + threadIdx.x;
        float v = s[threadIdx.x][threadIdx.y + j * 8] + emb[d * CC + c];
        size_t o = ((size_t)(b * CT + t) * 2 + d) * CC + c;
        split2(v, g_XEh[o], g_XEl[o]);
    }
}

// ---------------------------------------------------------------------------
// HMMA GEMM 128x256: D[m][n] = bias[n] + sum_k (Ah+Al)[m][k] * (Bh+Bl)[n][k]
// 512 threads, 16 warps (2x8), warp tile 64x32, 3-product bf16 split.
// MODE 0: fp32 row-major.  MODE 2: fp32 transposed (B, C, T).
// ---------------------------------------------------------------------------
__device__ __forceinline__ void load_chunk(
    uint32_t sbase,
    const __nv_bfloat16* __restrict__ Ah, const __nv_bfloat16* __restrict__ Al,
    int lda, int m0,
    const __nv_bfloat16* __restrict__ Bh, const __nv_bfloat16* __restrict__ Bl,
    int ldw, int n0, int kc, int tid)
{
    // A: 128 rows x 8 16B-chunks = 1024 slots (hi+lo per slot)
    #pragma unroll
    for (int t = 0; t < 2; t++) {
        int id = tid + t * 512;
        int r = id >> 3, j = id & 7;
        uint32_t off = SW128((uint32_t)(r * 128 + j * 16));
        size_t ga = (size_t)(m0 + r) * lda + (size_t)kc * BK + j * 8;
        cp16(sbase + off,         Ah + ga);
        cp16(sbase + 16384 + off, Al + ga);
    }
    // B: 256 rows x 8 = 2048 slots
    #pragma unroll
    for (int t = 0; t < 4; t++) {
        int id = tid + t * 512;
        int r = id >> 3, j = id & 7;
        uint32_t off = SW128((uint32_t)(r * 128 + j * 16));
        size_t gb = (size_t)(n0 + r) * ldw + (size_t)kc * BK + j * 8;
        cp16(sbase + 32768 + off, Bh + gb);
        cp16(sbase + 65536 + off, Bl + gb);
    }
    cp_commit();
}

template <int MODE, int NCHUNK>
__global__ void __launch_bounds__(512, 1)
k_tgemm(const __nv_bfloat16* __restrict__ Ah, const __nv_bfloat16* __restrict__ Al, int lda,
        const __nv_bfloat16* __restrict__ Bh, const __nv_bfloat16* __restrict__ Bl, int ldw,
        const float* __restrict__ bias,
        float* __restrict__ of, int ldc)
{
    extern __shared__ __align__(1024) char smem[];
    uint32_t sb = smem_u32(smem);
    int tid = threadIdx.x, lane = tid & 31, wid = tid >> 5;
    int m0 = blockIdx.y * BM, n0 = blockIdx.x * BN;
    int wm = (wid >> 3) * 64, wn = (wid & 7) * 32;

    float acc[4][4][4];
    #pragma unroll
    for (int a = 0; a < 4; a++)
        #pragma unroll
        for (int b = 0; b < 4; b++)
            #pragma unroll
            for (int c = 0; c < 4; c++) acc[a][b][c] = 0.f;

    uint32_t axor   = (uint32_t)(lane & 7) << 4;
    uint32_t arow   = (uint32_t)(wm + (lane & 15)) * 128;
    uint32_t achunk = (uint32_t)(lane >> 4) * 16;
    uint32_t brow   = (uint32_t)(wn + (lane & 7) + ((lane >> 4) << 3)) * 128;
    uint32_t bchunk = (uint32_t)((lane >> 3) & 1) * 16;

    load_chunk(sb,               Ah, Al, lda, m0, Bh, Bl, ldw, n0, 0, tid);
    if (NCHUNK > 1)
        load_chunk(sb + STAGE_BYTES, Ah, Al, lda, m0, Bh, Bl, ldw, n0, 1, tid);

    for (int i = 0; i < NCHUNK; i++) {
        if (i >= NCHUNK - 2) cp_wait0(); else cp_wait1();
        __syncthreads();
        uint32_t st = sb + (uint32_t)(i & 1) * STAGE_BYTES;

        #pragma unroll
        for (int ks = 0; ks < 4; ks++) {
            uint32_t act = ((uint32_t)(ks * 32) + achunk) ^ axor;
            uint32_t bct = ((uint32_t)(ks * 32) + bchunk) ^ axor;
            uint32_t ah[4][4], al[4][4], bh[2][4], bl[2][4];
            #pragma unroll
            for (int mi = 0; mi < 4; mi++) {
                uint32_t base = st + arow + (uint32_t)mi * 2048 + act;
                ldsm4(ah[mi], base);
                ldsm4(al[mi], base + 16384);
            }
            #pragma unroll
            for (int nj = 0; nj < 2; nj++) {
                uint32_t base = st + 32768 + brow + (uint32_t)nj * 2048 + bct;
                ldsm4(bh[nj], base);
                ldsm4(bl[nj], base + 32768);   // Bl is 32KB past Bh
            }
            #pragma unroll
            for (int mi = 0; mi < 4; mi++)
                #pragma unroll
                for (int ni = 0; ni < 4; ni++)
                    mma16816(acc[mi][ni], ah[mi], &bh[ni >> 1][(ni & 1) * 2]);
            #pragma unroll
            for (int mi = 0; mi < 4; mi++)
                #pragma unroll
                for (int ni = 0; ni < 4; ni++)
                    mma16816(acc[mi][ni], ah[mi], &bl[ni >> 1][(ni & 1) * 2]);
            #pragma unroll
            for (int mi = 0; mi < 4; mi++)
                #pragma unroll
                for (int ni = 0; ni < 4; ni++)
                    mma16816(acc[mi][ni], al[mi], &bh[ni >> 1][(ni & 1) * 2]);
        }
        __syncthreads();
        if (i + 2 < NCHUNK)
            load_chunk(sb + (uint32_t)(i & 1) * STAGE_BYTES,
                       Ah, Al, lda, m0, Bh, Bl, ldw, n0, i + 2, tid);
    }

    // epilogue: frags -> smem (+bias, stride 257 floats) -> coalesced stores
    float* epi = (float*)smem;
    int g = lane >> 2, t2 = (lane & 3) * 2;
    #pragma unroll
    for (int mi = 0; mi < 4; mi++) {
        #pragma unroll
        for (int ni = 0; ni < 4; ni++) {
            int r = wm + mi * 16 + g;
            int c = wn + ni * 8 + t2;
            float b0 = bias[n0 + c], b1 = bias[n0 + c + 1];
            epi[r * EPI_STRIDE + c]           = acc[mi][ni][0] + b0;
            epi[r * EPI_STRIDE + c + 1]       = acc[mi][ni][1] + b1;
            epi[(r + 8) * EPI_STRIDE + c]     = acc[mi][ni][2] + b0;
            epi[(r + 8) * EPI_STRIDE + c + 1] = acc[mi][ni][3] + b1;
        }
    }
    __syncthreads();

    if (MODE == 0) {
        #pragma unroll 4
        for (int idx = tid; idx < BM * BN; idx += 512) {
            int r = idx >> 8, c = idx & 255;
            of[(size_t)(m0 + r) * ldc + n0 + c] = epi[r * EPI_STRIDE + c];
        }
    } else {
        int b = m0 >> 11, tb = m0 & (CT - 1);
        #pragma unroll 4
        for (int idx = tid; idx < BM * BN; idx += 512) {
            int n = idx >> 7, tt = idx & 127;
            of[(size_t)b * (CC * CT) + (size_t)(n0 + n) * CT + tb + tt] =
                epi[tt * EPI_STRIDE + n];
        }
    }
}

// ---------------------------------------------------------------------------
// K3: tiny 2x2 attention; writes CTX hi/lo + per-token head-avg probs
// ---------------------------------------------------------------------------
__global__ void k_attn() {
    __shared__ float sp[2][CH][4];
    int tid = threadIdx.x;
    int local = tid >> 7;
    int token = blockIdx.x * 2 + local;
    int head = (tid >> 5) & 3;
    int lane = tid & 31;

    const float* base0 = g_QKV + (size_t)(2 * token) * (3 * CC);
    const float* base1 = base0 + 3 * CC;
    int col = head * CDH + lane;

    float q0[4], q1[4], k0[4], k1[4], v0[4], v1[4];
    #pragma unroll
    for (int r = 0; r < 4; r++) {
        int cc = col + 32 * r;
        q0[r] = base0[cc];            q1[r] = base1[cc];
        k0[r] = base0[CC + cc];       k1[r] = base1[CC + cc];
        v0[r] = base0[2 * CC + cc];   v1[r] = base1[2 * CC + cc];
    }
    float s00 = 0.f, s01 = 0.f, s10 = 0.f, s11 = 0.f;
    #pragma unroll
    for (int r = 0; r < 4; r++) {
        s00 += q0[r] * k0[r]; s01 += q0[r] * k1[r];
        s10 += q1[r] * k0[r]; s11 += q1[r] * k1[r];
    }
    #pragma unroll
    for (int o = 16; o > 0; o >>= 1) {
        s00 += __shfl_xor_sync(0xffffffffu, s00, o);
        s01 += __shfl_xor_sync(0xffffffffu, s01, o);
        s10 += __shfl_xor_sync(0xffffffffu, s10, o);
        s11 += __shfl_xor_sync(0xffffffffu, s11, o);
    }
    const float sc = 0.088388347648318447f;  // 1/sqrt(128)
    s00 *= sc; s01 *= sc; s10 *= sc; s11 *= sc;

    float mx0 = fmaxf(s00, s01);
    float e00 = expf(s00 - mx0), e01 = expf(s01 - mx0);
    float inv0 = 1.f / (e00 + e01);
    float p00 = e00 * inv0, p01 = e01 * inv0;

    float mx1 = fmaxf(s10, s11);
    float e10 = expf(s10 - mx1), e11 = expf(s11 - mx1);
    float inv1 = 1.f / (e10 + e11);
    float p10 = e10 * inv1, p11 = e11 * inv1;

    size_t row0 = (size_t)(2 * token) * CC;
    #pragma unroll
    for (int r = 0; r < 4; r++) {
        int cc = col + 32 * r;
        float c0 = p00 * v0[r] + p01 * v1[r];
        float c1 = p10 * v0[r] + p11 * v1[r];
        split2(c0, g_CTXh[row0 + cc],      g_CTXl[row0 + cc]);
        split2(c1, g_CTXh[row0 + CC + cc], g_CTXl[row0 + CC + cc]);
    }
    if (lane == 0) {
        sp[local][head][0] = p00; sp[local][head][1] = p01;
        sp[local][head][2] = p10; sp[local][head][3] = p11;
    }
    __syncthreads();
    if ((tid & 127) < 4) {
        int j = tid & 3;
        float s = (sp[local][0][j] + sp[local][1][j]) +
                  (sp[local][2][j] + sp[local][3][j]);
        g_PATT[(size_t)token * 4 + j] = s * 0.25f;
    }
}

// ---------------------------------------------------------------------------
// K7: avg_attention tail
// ---------------------------------------------------------------------------
__global__ void k_avg(float* __restrict__ out) {
    __shared__ float red[256];
    int b = blockIdx.x;
    for (int j = 0; j < 4; j++) {
        float s = 0.f;
        for (int t = threadIdx.x; t < CT; t += 256)
            s += g_PATT[((size_t)b * CT + t) * 4 + j];
        red[threadIdx.x] = s;
        __syncthreads();
        for (int w = 128; w > 0; w >>= 1) {
            if (threadIdx.x < w) red[threadIdx.x] += red[threadIdx.x + w];
            __syncthreads();
        }
        if (threadIdx.x == 0)
            out[(size_t)CB * CC * CT + b * 4 + j] = red[0] * (1.0f / CT);
        __syncthreads();
    }
}

// ---------------------------------------------------------------------------
// Host launcher (graph-capturable: kernel launches only)
// ---------------------------------------------------------------------------
extern "C" void kernel_launch(void* const* d_in, const int* in_sizes, int n_in,
                              void* d_out, int out_size) {
    const float* x   = (const float*)d_in[0];
    const float* emb = (const float*)d_in[1];
    const float* w1  = (const float*)d_in[2];
    const float* b1  = (const float*)d_in[3];
    const float* wo  = (const float*)d_in[4];
    const float* bo  = (const float*)d_in[5];
    const float* wp  = (const float*)d_in[6];
    const float* bp  = (const float*)d_in[7];
    const float* wim = (const float*)d_in[8];
    const float* bim = (const float*)d_in[9];
    const float* w2  = (const float*)d_in[10];
    const float* b2  = (const float*)d_in[11];
    float* out = (float*)d_out;

    __nv_bfloat16 *xeh, *xel, *ctxh, *ctxl, *w1h, *w1l, *uh, *ul;
    float *qkv, *s1, *s2, *u, *bt;
    cudaGetSymbolAddress((void**)&xeh,  g_XEh);  cudaGetSymbolAddress((void**)&xel,  g_XEl);
    cudaGetSymbolAddress((void**)&qkv,  g_QKV);
    cudaGetSymbolAddress((void**)&ctxh, g_CTXh); cudaGetSymbolAddress((void**)&ctxl, g_CTXl);
    cudaGetSymbolAddress((void**)&w1h,  g_W1h);  cudaGetSymbolAddress((void**)&w1l,  g_W1l);
    cudaGetSymbolAddress((void**)&s1,   g_S1);   cudaGetSymbolAddress((void**)&s2,   g_S2);
    cudaGetSymbolAddress((void**)&u,    g_U);
    cudaGetSymbolAddress((void**)&uh,   g_Uh);   cudaGetSymbolAddress((void**)&ul,   g_Ul);
    cudaGetSymbolAddress((void**)&bt,   g_BT);

    cudaFuncSetAttribute(k_tgemm<0, 8>,  cudaFuncAttributeMaxDynamicSharedMemorySize, SMEM_TOTAL);
    cudaFuncSetAttribute(k_tgemm<2, 16>, cudaFuncAttributeMaxDynamicSharedMemorySize, SMEM_TOTAL);

    // --- weight preprocessing (split-K SGEMMs; partial buffer reused serially) ---
    k_cvt<<<(3 * CC * CC + 255) / 256, 256>>>(w1, w1h, w1l, 3 * CC * CC);
    k_snn<<<dim3(8, 8, 8), 256>>>(wp,  CC, wo, CC);
    k_sred<<<CC, 256>>>(s1, CC);
    k_snn<<<dim3(8, 8, 8), 256>>>(wim, CC, wo, CC);
    k_sred<<<CC, 256>>>(s2, CC);
    k_snn<<<dim3(8, 8, 8), 256>>>(w2, 2 * CC, s1, CC);
    k_sred<<<CC, 256>>>(u, 2 * CC);
    k_snn<<<dim3(8, 8, 8), 256>>>(w2 + CC, 2 * CC, s2, CC);
    k_sred<<<CC, 256>>>(u + CC, 2 * CC);
    k_cvt<<<(CC * 2 * CC + 255) / 256, 256>>>(u, uh, ul, CC * 2 * CC);
    k_bias1<<<4, 128>>>(wp, bp, wim, bim, bo);
    k_bias2<<<4, 128>>>(w2, b2);

    // --- main pipeline ---
    k_embed<<<dim3(CT / 32, CC / 32, CB * 2), dim3(32, 8)>>>(x, emb);

    // GEMM1: QKV (65536 x 1536, K=512) -> fp32
    k_tgemm<0, 8><<<dim3(3 * CC / BN, NROW / BM), 512, SMEM_TOTAL>>>(
        xeh, xel, CC, w1h, w1l, CC, b1, qkv, 3 * CC);

    // attention -> ctx hi/lo (contiguous (NTOK, 1024) view)
    k_attn<<<NTOK / 2, 256>>>();

    // Fused out_proj+phone/imu+output: (32768 x 512, K=1024), transposed store
    k_tgemm<2, 16><<<dim3(CC / BN, NTOK / BM), 512, SMEM_TOTAL>>>(
        ctxh, ctxl, 2 * CC, uh, ul, 2 * CC, bt, out, 0);

    // avg_attention tail
    k_avg<<<CB, 256>>>(out);
}

// round 9
// speedup vs baseline: 1.0401x; 1.0401x over previous
#include <cuda_runtime.h>
#include <cuda_bf16.h>
#include <cstdint>
#include <math.h>

// Problem constants
#define CB   16
#define CT   2048
#define CC   512
#define CH   4
#define CDH  128
#define NTOK (CB * CT)     // 32768 tokens
#define NROW (NTOK * 2)    // 65536 token-device rows

// GEMM tiling (R7 proven config)
#define BM 128
#define BN 128
#define BK 64
#define STAGE_BYTES 65536          // Ah|Al|Bh|Bl each 16KB
#define SMEM_TOTAL  131072         // 2 stages

#define SW128(off) ((off) ^ (((off) >> 3) & 0x70))

// ---------------------------------------------------------------------------
// Scratch (static __device__; no runtime allocation)
// ---------------------------------------------------------------------------
__device__ __nv_bfloat16 g_XEh [(size_t)NROW * CC];
__device__ __nv_bfloat16 g_XEl [(size_t)NROW * CC];
__device__ float         g_QKV [(size_t)NROW * 3 * CC];
__device__ __nv_bfloat16 g_CTXh[(size_t)NROW * CC];   // viewed as (NTOK, 1024)
__device__ __nv_bfloat16 g_CTXl[(size_t)NROW * CC];
__device__ float         g_PATT[(size_t)NTOK * 4];
__device__ __nv_bfloat16 g_W1h[3 * CC * CC], g_W1l[3 * CC * CC];
// fused-weight pipeline
__device__ float         g_PART[16 * CC * CC];        // split-K partials (16 MB)
__device__ float         g_S1[CC * CC];               // W2a @ Wp
__device__ float         g_S2[CC * CC];               // W2b @ Wi
__device__ float         g_U [CC * 2 * CC];           // [S1@Wo | S2@Wo] (512, 1024)
__device__ __nv_bfloat16 g_Uh[CC * 2 * CC], g_Ul[CC * 2 * CC];
__device__ float         g_BB[2 * CC];                // Wp@bo+bp, Wi@bo+bi
__device__ float         g_BT[CC];                    // combined output bias

// ---------------------------------------------------------------------------
// Helpers
// ---------------------------------------------------------------------------
__device__ __forceinline__ uint32_t smem_u32(const void* p) {
    uint32_t a;
    asm("{ .reg .u64 t; cvta.to.shared.u64 t, %1; cvt.u32.u64 %0, t; }" : "=r"(a) : "l"(p));
    return a;
}
__device__ __forceinline__ void cp16(uint32_t dst, const void* src) {
    unsigned long long g = (unsigned long long)__cvta_generic_to_global(src);
    asm volatile("cp.async.cg.shared.global [%0], [%1], 16;" :: "r"(dst), "l"(g) : "memory");
}
__device__ __forceinline__ void cp_commit() { asm volatile("cp.async.commit_group;" ::: "memory"); }
__device__ __forceinline__ void cp_wait1()  { asm volatile("cp.async.wait_group 1;" ::: "memory"); }
__device__ __forceinline__ void cp_wait0()  { asm volatile("cp.async.wait_group 0;" ::: "memory"); }

__device__ __forceinline__ void ldsm4(uint32_t* r, uint32_t addr) {
    asm volatile("ldmatrix.sync.aligned.m8n8.x4.shared.b16 {%0,%1,%2,%3}, [%4];"
                 : "=r"(r[0]), "=r"(r[1]), "=r"(r[2]), "=r"(r[3]) : "r"(addr));
}
__device__ __forceinline__ void mma16816(float* d, const uint32_t* a, const uint32_t* b) {
    asm volatile(
        "mma.sync.aligned.m16n8k16.row.col.f32.bf16.bf16.f32 "
        "{%0,%1,%2,%3}, {%4,%5,%6,%7}, {%8,%9}, {%0,%1,%2,%3};"
        : "+f"(d[0]), "+f"(d[1]), "+f"(d[2]), "+f"(d[3])
        : "r"(a[0]), "r"(a[1]), "r"(a[2]), "r"(a[3]), "r"(b[0]), "r"(b[1]));
}
__device__ __forceinline__ void split2(float v, __nv_bfloat16& h, __nv_bfloat16& l) {
    h = __float2bfloat16(v);
    l = __float2bfloat16(v - __bfloat162float(h));
}

// ---------------------------------------------------------------------------
// K0: fp32 -> hi/lo bf16
// ---------------------------------------------------------------------------
__global__ void k_cvt(const float* __restrict__ s, __nv_bfloat16* __restrict__ h,
                      __nv_bfloat16* __restrict__ l, int n) {
    int i = blockIdx.x * 256 + threadIdx.x;
    if (i < n) split2(s[i], h[i], l[i]);
}

// ---------------------------------------------------------------------------
// Paired split-K fp32 SGEMM: TWO independent C = A @ B products in one
// launch. grid (8, 8, 16): z>>3 selects product, z&7 the K-slice.
// 64x64 tile, K-slice 64. Shared rows padded to 68 floats (16B multiple).
// ---------------------------------------------------------------------------
__global__ void __launch_bounds__(256)
k_snn2(const float* __restrict__ A0, int lda0, const float* __restrict__ B0, int ldb0,
       const float* __restrict__ A1, int lda1, const float* __restrict__ B1, int ldb1) {
    __shared__ __align__(16) float As[64][68];   // [k][m]
    __shared__ __align__(16) float Bs[64][68];   // [k][n]
    int tid = threadIdx.x;
    int p = blockIdx.z >> 3, kz = blockIdx.z & 7;
    const float* A = p ? A1 : A0;  int lda = p ? lda1 : lda0;
    const float* B = p ? B1 : B0;  int ldb = p ? ldb1 : ldb0;
    int n0 = blockIdx.x * 64, m0 = blockIdx.y * 64;
    int k0 = kz * 64;
    int tr = tid / 16, tc = tid % 16;
    int lr = tid / 16, lc4 = (tid % 16) * 4;

    #pragma unroll
    for (int h = 0; h < 4; h++) {
        int r = lr + h * 16;
        float4 a = *(const float4*)(A + (size_t)(m0 + r) * lda + k0 + lc4);
        As[lc4 + 0][r] = a.x; As[lc4 + 1][r] = a.y;
        As[lc4 + 2][r] = a.z; As[lc4 + 3][r] = a.w;
        *(float4*)&Bs[r][lc4] = *(const float4*)(B + (size_t)(k0 + r) * ldb + n0 + lc4);
    }
    __syncthreads();

    float acc[4][4];
    #pragma unroll
    for (int i = 0; i < 4; i++)
        #pragma unroll
        for (int j = 0; j < 4; j++) acc[i][j] = 0.f;

    #pragma unroll 8
    for (int k = 0; k < 64; k++) {
        float4 ra = *(const float4*)&As[k][tr * 4];
        float4 rb = *(const float4*)&Bs[k][tc * 4];
        float a[4] = {ra.x, ra.y, ra.z, ra.w};
        float b[4] = {rb.x, rb.y, rb.z, rb.w};
        #pragma unroll
        for (int i = 0; i < 4; i++)
            #pragma unroll
            for (int j = 0; j < 4; j++)
                acc[i][j] += a[i] * b[j];
    }

    float* part = g_PART + (size_t)blockIdx.z * CC * CC;
    #pragma unroll
    for (int i = 0; i < 4; i++)
        *(float4*)(part + (size_t)(m0 + tr * 4 + i) * CC + n0 + tc * 4) =
            make_float4(acc[i][0], acc[i][1], acc[i][2], acc[i][3]);
}

// paired reduce: product p = blockIdx.y reduces slices p*8..p*8+7 (fixed order)
__global__ void __launch_bounds__(256)
k_sred2(float* __restrict__ d0, int ldc0, float* __restrict__ d1, int ldc1) {
    int p = blockIdx.y;
    float* dst = p ? d1 : d0;
    int ldc = p ? ldc1 : ldc0;
    const float* base = g_PART + (size_t)p * 8 * CC * CC;
    int m = blockIdx.x;
    int n = threadIdx.x * 2;
    #pragma unroll
    for (int q = 0; q < 2; q++) {
        float s = 0.f;
        #pragma unroll
        for (int sl = 0; sl < 8; sl++)
            s += base[(size_t)sl * CC * CC + (size_t)m * CC + n + q];
        dst[(size_t)m * ldc + n + q] = s;
    }
}

// ---------------------------------------------------------------------------
// Bias folding
// ---------------------------------------------------------------------------
__global__ void k_bias1(const float* __restrict__ wp, const float* __restrict__ bp,
                        const float* __restrict__ wi, const float* __restrict__ bi,
                        const float* __restrict__ bo) {
    int i = threadIdx.x + blockIdx.x * 128;
    float s0 = bp[i], s1 = bi[i];
    for (int k = 0; k < CC; k++) {
        float b = bo[k];
        s0 += wp[i * CC + k] * b;
        s1 += wi[i * CC + k] * b;
    }
    g_BB[i] = s0;
    g_BB[CC + i] = s1;
}
__global__ void k_bias2(const float* __restrict__ w2, const float* __restrict__ b2) {
    int n = threadIdx.x + blockIdx.x * 128;
    float s = b2[n];
    for (int a = 0; a < CC; a++)
        s += w2[n * 2 * CC + a] * g_BB[a] + w2[n * 2 * CC + CC + a] * g_BB[CC + a];
    g_BT[n] = s;
}

// ---------------------------------------------------------------------------
// K1: x (B, C, 2, T) -> XE hi/lo with device embedding
// ---------------------------------------------------------------------------
__global__ void k_embed(const float* __restrict__ x, const float* __restrict__ emb) {
    __shared__ float s[32][33];
    int t0 = blockIdx.x * 32;
    int c0 = blockIdx.y * 32;
    int bd = blockIdx.z;
    int b = bd >> 1, d = bd & 1;

    #pragma unroll
    for (int j = 0; j < 4; j++) {
        int c = c0 + threadIdx.y + j * 8;
        s[threadIdx.y + j * 8][threadIdx.x] =
            x[(((size_t)b * CC + c) * 2 + d) * CT + t0 + threadIdx.x];
    }
    __syncthreads();
    #pragma unroll
    for (int j = 0; j < 4; j++) {
        int t = t0 + threadIdx.y + j * 8;
        int c = c0 + threadIdx.x;
        float v = s[threadIdx.x][threadIdx.y + j * 8] + emb[d * CC + c];
        size_t o = ((size_t)(b * CT + t) * 2 + d) * CC + c;
        split2(v, g_XEh[o], g_XEl[o]);
    }
}

// ---------------------------------------------------------------------------
// HMMA GEMM (R7 proven): D[m][n] = bias[n] + sum_k (Ah+Al)[m][k]*(Bh+Bl)[n][k]
// MODE 0: fp32 row-major.  MODE 2: fp32 transposed (B, C, T).
// ---------------------------------------------------------------------------
__device__ __forceinline__ void load_chunk(
    uint32_t sbase,
    const __nv_bfloat16* __restrict__ Ah, const __nv_bfloat16* __restrict__ Al,
    int lda, int m0,
    const __nv_bfloat16* __restrict__ Bh, const __nv_bfloat16* __restrict__ Bl,
    int ldw, int n0, int kc, int tid)
{
    #pragma unroll
    for (int t = 0; t < 4; t++) {
        int id = tid + t * 256;
        int r = id >> 3, j = id & 7;
        uint32_t off = SW128((uint32_t)(r * 128 + j * 16));
        size_t ga = (size_t)(m0 + r) * lda + (size_t)kc * BK + j * 8;
        cp16(sbase + off,         Ah + ga);
        cp16(sbase + 16384 + off, Al + ga);
        size_t gb = (size_t)(n0 + r) * ldw + (size_t)kc * BK + j * 8;
        cp16(sbase + 32768 + off, Bh + gb);
        cp16(sbase + 49152 + off, Bl + gb);
    }
    cp_commit();
}

template <int MODE, int NCHUNK>
__global__ void __launch_bounds__(256, 1)
k_tgemm(const __nv_bfloat16* __restrict__ Ah, const __nv_bfloat16* __restrict__ Al, int lda,
        const __nv_bfloat16* __restrict__ Bh, const __nv_bfloat16* __restrict__ Bl, int ldw,
        const float* __restrict__ bias,
        float* __restrict__ of, int ldc)
{
    extern __shared__ __align__(1024) char smem[];
    uint32_t sb = smem_u32(smem);
    int tid = threadIdx.x, lane = tid & 31, wid = tid >> 5;
    int m0 = blockIdx.y * BM, n0 = blockIdx.x * BN;
    int wm = (wid >> 2) * 64, wn = (wid & 3) * 32;

    float acc[4][4][4];
    #pragma unroll
    for (int a = 0; a < 4; a++)
        #pragma unroll
        for (int b = 0; b < 4; b++)
            #pragma unroll
            for (int c = 0; c < 4; c++) acc[a][b][c] = 0.f;

    uint32_t axor   = (uint32_t)(lane & 7) << 4;
    uint32_t arow   = (uint32_t)(wm + (lane & 15)) * 128;
    uint32_t achunk = (uint32_t)(lane >> 4) * 16;
    uint32_t brow   = (uint32_t)(wn + (lane & 7) + ((lane >> 4) << 3)) * 128;
    uint32_t bchunk = (uint32_t)((lane >> 3) & 1) * 16;

    load_chunk(sb,               Ah, Al, lda, m0, Bh, Bl, ldw, n0, 0, tid);
    if (NCHUNK > 1)
        load_chunk(sb + STAGE_BYTES, Ah, Al, lda, m0, Bh, Bl, ldw, n0, 1, tid);

    for (int i = 0; i < NCHUNK; i++) {
        if (i >= NCHUNK - 2) cp_wait0(); else cp_wait1();
        __syncthreads();
        uint32_t st = sb + (uint32_t)(i & 1) * STAGE_BYTES;

        #pragma unroll
        for (int ks = 0; ks < 4; ks++) {
            uint32_t act = ((uint32_t)(ks * 32) + achunk) ^ axor;
            uint32_t bct = ((uint32_t)(ks * 32) + bchunk) ^ axor;
            uint32_t ah[4][4], al[4][4], bh[2][4], bl[2][4];
            #pragma unroll
            for (int mi = 0; mi < 4; mi++) {
                uint32_t base = st + arow + (uint32_t)mi * 2048 + act;
                ldsm4(ah[mi], base);
                ldsm4(al[mi], base + 16384);
            }
            #pragma unroll
            for (int nj = 0; nj < 2; nj++) {
                uint32_t base = st + 32768 + brow + (uint32_t)nj * 2048 + bct;
                ldsm4(bh[nj], base);
                ldsm4(bl[nj], base + 16384);
            }
            #pragma unroll
            for (int mi = 0; mi < 4; mi++)
                #pragma unroll
                for (int ni = 0; ni < 4; ni++)
                    mma16816(acc[mi][ni], ah[mi], &bh[ni >> 1][(ni & 1) * 2]);
            #pragma unroll
            for (int mi = 0; mi < 4; mi++)
                #pragma unroll
                for (int ni = 0; ni < 4; ni++)
                    mma16816(acc[mi][ni], ah[mi], &bl[ni >> 1][(ni & 1) * 2]);
            #pragma unroll
            for (int mi = 0; mi < 4; mi++)
                #pragma unroll
                for (int ni = 0; ni < 4; ni++)
                    mma16816(acc[mi][ni], al[mi], &bh[ni >> 1][(ni & 1) * 2]);
        }
        __syncthreads();
        if (i + 2 < NCHUNK)
            load_chunk(sb + (uint32_t)(i & 1) * STAGE_BYTES,
                       Ah, Al, lda, m0, Bh, Bl, ldw, n0, i + 2, tid);
    }

    // epilogue: frags -> padded smem (+bias) -> coalesced stores
    float* epi = (float*)smem;
    int g = lane >> 2, t2 = (lane & 3) * 2;
    #pragma unroll
    for (int mi = 0; mi < 4; mi++) {
        #pragma unroll
        for (int ni = 0; ni < 4; ni++) {
            int r = wm + mi * 16 + g;
            int c = wn + ni * 8 + t2;
            float b0 = bias[n0 + c], b1 = bias[n0 + c + 1];
            epi[r * 132 + c]           = acc[mi][ni][0] + b0;
            epi[r * 132 + c + 1]       = acc[mi][ni][1] + b1;
            epi[(r + 8) * 132 + c]     = acc[mi][ni][2] + b0;
            epi[(r + 8) * 132 + c + 1] = acc[mi][ni][3] + b1;
        }
    }
    __syncthreads();

    if (MODE == 0) {
        #pragma unroll 4
        for (int idx = tid; idx < BM * BN; idx += 256) {
            int r = idx >> 7, c = idx & 127;
            of[(size_t)(m0 + r) * ldc + n0 + c] = epi[r * 132 + c];
        }
    } else {
        int b = m0 >> 11, tb = m0 & (CT - 1);
        #pragma unroll 4
        for (int idx = tid; idx < BM * BN; idx += 256) {
            int n = idx >> 7, tt = idx & 127;
            of[(size_t)b * (CC * CT) + (size_t)(n0 + n) * CT + tb + tt] = epi[tt * 132 + n];
        }
    }
}

// ---------------------------------------------------------------------------
// K3: tiny 2x2 attention (vectorized); CTX hi/lo + per-token head-avg probs.
// Each lane owns 4 contiguous dims of its head (float4 loads, bf162 stores).
// ---------------------------------------------------------------------------
__global__ void k_attn() {
    __shared__ float sp[2][CH][4];
    int tid = threadIdx.x;
    int local = tid >> 7;
    int token = blockIdx.x * 2 + local;
    int head = (tid >> 5) & 3;
    int lane = tid & 31;

    const float* base0 = g_QKV + (size_t)(2 * token) * (3 * CC);
    const float* base1 = base0 + 3 * CC;
    int col4 = head * CDH + lane * 4;

    float4 q0 = *(const float4*)(base0 + col4);
    float4 k0 = *(const float4*)(base0 + CC + col4);
    float4 v0 = *(const float4*)(base0 + 2 * CC + col4);
    float4 q1 = *(const float4*)(base1 + col4);
    float4 k1 = *(const float4*)(base1 + CC + col4);
    float4 v1 = *(const float4*)(base1 + 2 * CC + col4);

    float s00 = q0.x * k0.x + q0.y * k0.y + q0.z * k0.z + q0.w * k0.w;
    float s01 = q0.x * k1.x + q0.y * k1.y + q0.z * k1.z + q0.w * k1.w;
    float s10 = q1.x * k0.x + q1.y * k0.y + q1.z * k0.z + q1.w * k0.w;
    float s11 = q1.x * k1.x + q1.y * k1.y + q1.z * k1.z + q1.w * k1.w;

    #pragma unroll
    for (int o = 16; o > 0; o >>= 1) {
        s00 += __shfl_xor_sync(0xffffffffu, s00, o);
        s01 += __shfl_xor_sync(0xffffffffu, s01, o);
        s10 += __shfl_xor_sync(0xffffffffu, s10, o);
        s11 += __shfl_xor_sync(0xffffffffu, s11, o);
    }
    const float sc = 0.088388347648318447f;  // 1/sqrt(128)
    s00 *= sc; s01 *= sc; s10 *= sc; s11 *= sc;

    float mx0 = fmaxf(s00, s01);
    float e00 = expf(s00 - mx0), e01 = expf(s01 - mx0);
    float inv0 = 1.f / (e00 + e01);
    float p00 = e00 * inv0, p01 = e01 * inv0;

    float mx1 = fmaxf(s10, s11);
    float e10 = expf(s10 - mx1), e11 = expf(s11 - mx1);
    float inv1 = 1.f / (e10 + e11);
    float p10 = e10 * inv1, p11 = e11 * inv1;

    size_t row0 = (size_t)(2 * token) * CC;
    float c0[4] = {p00 * v0.x + p01 * v1.x, p00 * v0.y + p01 * v1.y,
                   p00 * v0.z + p01 * v1.z, p00 * v0.w + p01 * v1.w};
    float c1[4] = {p10 * v0.x + p11 * v1.x, p10 * v0.y + p11 * v1.y,
                   p10 * v0.z + p11 * v1.z, p10 * v0.w + p11 * v1.w};

    __nv_bfloat16 h[4], l[4];
    #pragma unroll
    for (int j = 0; j < 4; j++) split2(c0[j], h[j], l[j]);
    *(__nv_bfloat162*)(g_CTXh + row0 + col4)     = __nv_bfloat162(h[0], h[1]);
    *(__nv_bfloat162*)(g_CTXh + row0 + col4 + 2) = __nv_bfloat162(h[2], h[3]);
    *(__nv_bfloat162*)(g_CTXl + row0 + col4)     = __nv_bfloat162(l[0], l[1]);
    *(__nv_bfloat162*)(g_CTXl + row0 + col4 + 2) = __nv_bfloat162(l[2], l[3]);
    #pragma unroll
    for (int j = 0; j < 4; j++) split2(c1[j], h[j], l[j]);
    *(__nv_bfloat162*)(g_CTXh + row0 + CC + col4)     = __nv_bfloat162(h[0], h[1]);
    *(__nv_bfloat162*)(g_CTXh + row0 + CC + col4 + 2) = __nv_bfloat162(h[2], h[3]);
    *(__nv_bfloat162*)(g_CTXl + row0 + CC + col4)     = __nv_bfloat162(l[0], l[1]);
    *(__nv_bfloat162*)(g_CTXl + row0 + CC + col4 + 2) = __nv_bfloat162(l[2], l[3]);

    if (lane == 0) {
        sp[local][head][0] = p00; sp[local][head][1] = p01;
        sp[local][head][2] = p10; sp[local][head][3] = p11;
    }
    __syncthreads();
    if ((tid & 127) < 4) {
        int j = tid & 3;
        float s = (sp[local][0][j] + sp[local][1][j]) +
                  (sp[local][2][j] + sp[local][3][j]);
        g_PATT[(size_t)token * 4 + j] = s * 0.25f;
    }
}

// ---------------------------------------------------------------------------
// K7: avg_attention tail
// ---------------------------------------------------------------------------
__global__ void k_avg(float* __restrict__ out) {
    __shared__ float red[256];
    int b = blockIdx.x;
    for (int j = 0; j < 4; j++) {
        float s = 0.f;
        for (int t = threadIdx.x; t < CT; t += 256)
            s += g_PATT[((size_t)b * CT + t) * 4 + j];
        red[threadIdx.x] = s;
        __syncthreads();
        for (int w = 128; w > 0; w >>= 1) {
            if (threadIdx.x < w) red[threadIdx.x] += red[threadIdx.x + w];
            __syncthreads();
        }
        if (threadIdx.x == 0)
            out[(size_t)CB * CC * CT + b * 4 + j] = red[0] * (1.0f / CT);
        __syncthreads();
    }
}

// ---------------------------------------------------------------------------
// Host launcher (graph-capturable: kernel launches only)
// ---------------------------------------------------------------------------
extern "C" void kernel_launch(void* const* d_in, const int* in_sizes, int n_in,
                              void* d_out, int out_size) {
    const float* x   = (const float*)d_in[0];
    const float* emb = (const float*)d_in[1];
    const float* w1  = (const float*)d_in[2];
    const float* b1  = (const float*)d_in[3];
    const float* wo  = (const float*)d_in[4];
    const float* bo  = (const float*)d_in[5];
    const float* wp  = (const float*)d_in[6];
    const float* bp  = (const float*)d_in[7];
    const float* wim = (const float*)d_in[8];
    const float* bim = (const float*)d_in[9];
    const float* w2  = (const float*)d_in[10];
    const float* b2  = (const float*)d_in[11];
    float* out = (float*)d_out;

    __nv_bfloat16 *xeh, *xel, *ctxh, *ctxl, *w1h, *w1l, *uh, *ul;
    float *qkv, *s1, *s2, *u, *bt;
    cudaGetSymbolAddress((void**)&xeh,  g_XEh);  cudaGetSymbolAddress((void**)&xel,  g_XEl);
    cudaGetSymbolAddress((void**)&qkv,  g_QKV);
    cudaGetSymbolAddress((void**)&ctxh, g_CTXh); cudaGetSymbolAddress((void**)&ctxl, g_CTXl);
    cudaGetSymbolAddress((void**)&w1h,  g_W1h);  cudaGetSymbolAddress((void**)&w1l,  g_W1l);
    cudaGetSymbolAddress((void**)&s1,   g_S1);   cudaGetSymbolAddress((void**)&s2,   g_S2);
    cudaGetSymbolAddress((void**)&u,    g_U);
    cudaGetSymbolAddress((void**)&uh,   g_Uh);   cudaGetSymbolAddress((void**)&ul,   g_Ul);
    cudaGetSymbolAddress((void**)&bt,   g_BT);

    cudaFuncSetAttribute(k_tgemm<0, 8>,  cudaFuncAttributeMaxDynamicSharedMemorySize, SMEM_TOTAL);
    cudaFuncSetAttribute(k_tgemm<2, 16>, cudaFuncAttributeMaxDynamicSharedMemorySize, SMEM_TOTAL);

    // --- weight preprocessing (paired split-K SGEMMs: U = (W2a@Wp)@Wo etc.) ---
    k_cvt<<<(3 * CC * CC + 255) / 256, 256>>>(w1, w1h, w1l, 3 * CC * CC);
    // stage 1: S1 = W2a @ Wp, S2 = W2b @ Wi   (one launch)
    k_snn2<<<dim3(8, 8, 16), 256>>>(w2, 2 * CC, wp, CC, w2 + CC, 2 * CC, wim, CC);
    k_sred2<<<dim3(CC, 2), 256>>>(s1, CC, s2, CC);
    // stage 2: U = [S1 @ Wo | S2 @ Wo]        (one launch)
    k_snn2<<<dim3(8, 8, 16), 256>>>(s1, CC, wo, CC, s2, CC, wo, CC);
    k_sred2<<<dim3(CC, 2), 256>>>(u, 2 * CC, u + CC, 2 * CC);
    k_cvt<<<(CC * 2 * CC + 255) / 256, 256>>>(u, uh, ul, CC * 2 * CC);
    k_bias1<<<4, 128>>>(wp, bp, wim, bim, bo);
    k_bias2<<<4, 128>>>(w2, b2);

    // --- main pipeline ---
    k_embed<<<dim3(CT / 32, CC / 32, CB * 2), dim3(32, 8)>>>(x, emb);

    // GEMM1: QKV (65536 x 1536, K=512) -> fp32
    k_tgemm<0, 8><<<dim3(3 * CC / BN, NROW / BM), 256, SMEM_TOTAL>>>(
        xeh, xel, CC, w1h, w1l, CC, b1, qkv, 3 * CC);

    // attention -> ctx hi/lo (contiguous (NTOK, 1024) view)
    k_attn<<<NTOK / 2, 256>>>();

    // Fused out_proj+phone/imu+output: (32768 x 512, K=1024), transposed store
    k_tgemm<2, 16><<<dim3(CC / BN, NTOK / BM), 256, SMEM_TOTAL>>>(
        ctxh, ctxl, 2 * CC, uh, ul, 2 * CC, bt, out, 0);

    // avg_attention tail
    k_avg<<<CB, 256>>>(out);
}

// round 11
// speedup vs baseline: 1.4757x; 1.4188x over previous
#include <cuda_runtime.h>
#include <cuda_fp16.h>
#include <cstdint>
#include <math.h>

// Problem constants
#define CB   16
#define CT   2048
#define CC   512
#define CH   4
#define CDH  128
#define NTOK (CB * CT)     // 32768 tokens
#define NROW (NTOK * 2)    // 65536 token-device rows

// GEMM tiling: 128x128 tile, BK=64, fp16 2-product scheme
#define BM 128
#define BN 128
#define BK 64
#define STAGE_BYTES 49152          // A 16K | Bh 16K | Bl 16K
#define SMEM_TOTAL  98304          // 2 stages (2 CTAs/SM possible)

#define SW128(off) ((off) ^ (((off) >> 3) & 0x70))

// ---------------------------------------------------------------------------
// Scratch (static __device__; no runtime allocation)
// ---------------------------------------------------------------------------
__device__ __half g_XE [(size_t)NROW * CC];           // single fp16 activations
__device__ float  g_QKV[(size_t)NROW * 3 * CC];
__device__ __half g_CTX[(size_t)NROW * CC];           // viewed as (NTOK, 1024)
__device__ float  g_PATT[(size_t)NTOK * 4];
__device__ __half g_W1h[3 * CC * CC], g_W1l[3 * CC * CC];
// fused-weight pipeline
__device__ float  g_PART[16 * CC * CC];               // split-K partials
__device__ float  g_S1[CC * CC];                      // W2a @ Wp
__device__ float  g_S2[CC * CC];                      // W2b @ Wi
__device__ float  g_U [CC * 2 * CC];                  // [S1@Wo | S2@Wo]
__device__ __half g_Uh[CC * 2 * CC], g_Ul[CC * 2 * CC];
__device__ float  g_BB[2 * CC];
__device__ float  g_BT[CC];

// ---------------------------------------------------------------------------
// Helpers
// ---------------------------------------------------------------------------
__device__ __forceinline__ uint32_t smem_u32(const void* p) {
    uint32_t a;
    asm("{ .reg .u64 t; cvta.to.shared.u64 t, %1; cvt.u32.u64 %0, t; }" : "=r"(a) : "l"(p));
    return a;
}
__device__ __forceinline__ void cp16(uint32_t dst, const void* src) {
    unsigned long long g = (unsigned long long)__cvta_generic_to_global(src);
    asm volatile("cp.async.cg.shared.global [%0], [%1], 16;" :: "r"(dst), "l"(g) : "memory");
}
__device__ __forceinline__ void cp_commit() { asm volatile("cp.async.commit_group;" ::: "memory"); }
__device__ __forceinline__ void cp_wait1()  { asm volatile("cp.async.wait_group 1;" ::: "memory"); }
__device__ __forceinline__ void cp_wait0()  { asm volatile("cp.async.wait_group 0;" ::: "memory"); }

__device__ __forceinline__ void ldsm4(uint32_t* r, uint32_t addr) {
    asm volatile("ldmatrix.sync.aligned.m8n8.x4.shared.b16 {%0,%1,%2,%3}, [%4];"
                 : "=r"(r[0]), "=r"(r[1]), "=r"(r[2]), "=r"(r[3]) : "r"(addr));
}
__device__ __forceinline__ void mma16816(float* d, const uint32_t* a, const uint32_t* b) {
    asm volatile(
        "mma.sync.aligned.m16n8k16.row.col.f32.f16.f16.f32 "
        "{%0,%1,%2,%3}, {%4,%5,%6,%7}, {%8,%9}, {%0,%1,%2,%3};"
        : "+f"(d[0]), "+f"(d[1]), "+f"(d[2]), "+f"(d[3])
        : "r"(a[0]), "r"(a[1]), "r"(a[2]), "r"(a[3]), "r"(b[0]), "r"(b[1]));
}
__device__ __forceinline__ void split2h(float v, __half& h, __half& l) {
    h = __float2half(v);
    l = __float2half(v - __half2float(h));
}

// ---------------------------------------------------------------------------
// K0: fp32 -> hi/lo fp16 (weights only; exact to ~2^-22)
// ---------------------------------------------------------------------------
__global__ void k_cvt(const float* __restrict__ s, __half* __restrict__ h,
                      __half* __restrict__ l, int n) {
    int i = blockIdx.x * 256 + threadIdx.x;
    if (i < n) split2h(s[i], h[i], l[i]);
}

// ---------------------------------------------------------------------------
// Paired split-K fp32 SGEMM (preamble): two C = A @ B in one launch.
// grid (8, 8, 16): z>>3 selects product, z&7 the K-slice. Rows padded to 68.
// ---------------------------------------------------------------------------
__global__ void __launch_bounds__(256)
k_snn2(const float* __restrict__ A0, int lda0, const float* __restrict__ B0, int ldb0,
       const float* __restrict__ A1, int lda1, const float* __restrict__ B1, int ldb1) {
    __shared__ __align__(16) float As[64][68];
    __shared__ __align__(16) float Bs[64][68];
    int tid = threadIdx.x;
    int p = blockIdx.z >> 3, kz = blockIdx.z & 7;
    const float* A = p ? A1 : A0;  int lda = p ? lda1 : lda0;
    const float* B = p ? B1 : B0;  int ldb = p ? ldb1 : ldb0;
    int n0 = blockIdx.x * 64, m0 = blockIdx.y * 64;
    int k0 = kz * 64;
    int tr = tid / 16, tc = tid % 16;
    int lr = tid / 16, lc4 = (tid % 16) * 4;

    #pragma unroll
    for (int h = 0; h < 4; h++) {
        int r = lr + h * 16;
        float4 a = *(const float4*)(A + (size_t)(m0 + r) * lda + k0 + lc4);
        As[lc4 + 0][r] = a.x; As[lc4 + 1][r] = a.y;
        As[lc4 + 2][r] = a.z; As[lc4 + 3][r] = a.w;
        *(float4*)&Bs[r][lc4] = *(const float4*)(B + (size_t)(k0 + r) * ldb + n0 + lc4);
    }
    __syncthreads();

    float acc[4][4];
    #pragma unroll
    for (int i = 0; i < 4; i++)
        #pragma unroll
        for (int j = 0; j < 4; j++) acc[i][j] = 0.f;

    #pragma unroll 8
    for (int k = 0; k < 64; k++) {
        float4 ra = *(const float4*)&As[k][tr * 4];
        float4 rb = *(const float4*)&Bs[k][tc * 4];
        float a[4] = {ra.x, ra.y, ra.z, ra.w};
        float b[4] = {rb.x, rb.y, rb.z, rb.w};
        #pragma unroll
        for (int i = 0; i < 4; i++)
            #pragma unroll
            for (int j = 0; j < 4; j++)
                acc[i][j] += a[i] * b[j];
    }

    float* part = g_PART + (size_t)blockIdx.z * CC * CC;
    #pragma unroll
    for (int i = 0; i < 4; i++)
        *(float4*)(part + (size_t)(m0 + tr * 4 + i) * CC + n0 + tc * 4) =
            make_float4(acc[i][0], acc[i][1], acc[i][2], acc[i][3]);
}

__global__ void __launch_bounds__(256)
k_sred2(float* __restrict__ d0, int ldc0, float* __restrict__ d1, int ldc1) {
    int p = blockIdx.y;
    float* dst = p ? d1 : d0;
    int ldc = p ? ldc1 : ldc0;
    const float* base = g_PART + (size_t)p * 8 * CC * CC;
    int m = blockIdx.x;
    int n = threadIdx.x * 2;
    #pragma unroll
    for (int q = 0; q < 2; q++) {
        float s = 0.f;
        #pragma unroll
        for (int sl = 0; sl < 8; sl++)
            s += base[(size_t)sl * CC * CC + (size_t)m * CC + n + q];
        dst[(size_t)m * ldc + n + q] = s;
    }
}

// ---------------------------------------------------------------------------
// Bias folding
// ---------------------------------------------------------------------------
__global__ void k_bias1(const float* __restrict__ wp, const float* __restrict__ bp,
                        const float* __restrict__ wi, const float* __restrict__ bi,
                        const float* __restrict__ bo) {
    int i = threadIdx.x + blockIdx.x * 128;
    float s0 = bp[i], s1 = bi[i];
    for (int k = 0; k < CC; k++) {
        float b = bo[k];
        s0 += wp[i * CC + k] * b;
        s1 += wi[i * CC + k] * b;
    }
    g_BB[i] = s0;
    g_BB[CC + i] = s1;
}
__global__ void k_bias2(const float* __restrict__ w2, const float* __restrict__ b2) {
    int n = threadIdx.x + blockIdx.x * 128;
    float s = b2[n];
    for (int a = 0; a < CC; a++)
        s += w2[n * 2 * CC + a] * g_BB[a] + w2[n * 2 * CC + CC + a] * g_BB[CC + a];
    g_BT[n] = s;
}

// ---------------------------------------------------------------------------
// K1: x (B, C, 2, T) -> XE fp16 with device embedding
// ---------------------------------------------------------------------------
__global__ void k_embed(const float* __restrict__ x, const float* __restrict__ emb) {
    __shared__ float s[32][33];
    int t0 = blockIdx.x * 32;
    int c0 = blockIdx.y * 32;
    int bd = blockIdx.z;
    int b = bd >> 1, d = bd & 1;

    #pragma unroll
    for (int j = 0; j < 4; j++) {
        int c = c0 + threadIdx.y + j * 8;
        s[threadIdx.y + j * 8][threadIdx.x] =
            x[(((size_t)b * CC + c) * 2 + d) * CT + t0 + threadIdx.x];
    }
    __syncthreads();
    #pragma unroll
    for (int j = 0; j < 4; j++) {
        int t = t0 + threadIdx.y + j * 8;
        int c = c0 + threadIdx.x;
        float v = s[threadIdx.x][threadIdx.y + j * 8] + emb[d * CC + c];
        g_XE[((size_t)(b * CT + t) * 2 + d) * CC + c] = __float2half(v);
    }
}

// ---------------------------------------------------------------------------
// HMMA GEMM fp16 2-product: D[m][n] = bias[n] + sum_k A[m][k]*(Bh+Bl)[n][k]
// A single fp16; B weights split hi/lo. MODE 0: fp32 row-major.
// MODE 2: fp32 transposed (B, C, T).
// ---------------------------------------------------------------------------
__device__ __forceinline__ void load_chunk(
    uint32_t sbase,
    const __half* __restrict__ A, int lda, int m0,
    const __half* __restrict__ Bh, const __half* __restrict__ Bl,
    int ldw, int n0, int kc, int tid)
{
    #pragma unroll
    for (int t = 0; t < 4; t++) {
        int id = tid + t * 256;
        int r = id >> 3, j = id & 7;
        uint32_t off = SW128((uint32_t)(r * 128 + j * 16));
        size_t ga = (size_t)(m0 + r) * lda + (size_t)kc * BK + j * 8;
        cp16(sbase + off, A + ga);
        size_t gb = (size_t)(n0 + r) * ldw + (size_t)kc * BK + j * 8;
        cp16(sbase + 16384 + off, Bh + gb);
        cp16(sbase + 32768 + off, Bl + gb);
    }
    cp_commit();
}

template <int MODE, int NCHUNK>
__global__ void __launch_bounds__(256, 2)
k_tgemm(const __half* __restrict__ A, int lda,
        const __half* __restrict__ Bh, const __half* __restrict__ Bl, int ldw,
        const float* __restrict__ bias,
        float* __restrict__ of, int ldc)
{
    extern __shared__ __align__(1024) char smem[];
    uint32_t sb = smem_u32(smem);
    int tid = threadIdx.x, lane = tid & 31, wid = tid >> 5;
    int m0 = blockIdx.y * BM, n0 = blockIdx.x * BN;
    int wm = (wid >> 2) * 64, wn = (wid & 3) * 32;

    float acc[4][4][4];
    #pragma unroll
    for (int a = 0; a < 4; a++)
        #pragma unroll
        for (int b = 0; b < 4; b++)
            #pragma unroll
            for (int c = 0; c < 4; c++) acc[a][b][c] = 0.f;

    uint32_t axor   = (uint32_t)(lane & 7) << 4;
    uint32_t arow   = (uint32_t)(wm + (lane & 15)) * 128;
    uint32_t achunk = (uint32_t)(lane >> 4) * 16;
    uint32_t brow   = (uint32_t)(wn + (lane & 7) + ((lane >> 4) << 3)) * 128;
    uint32_t bchunk = (uint32_t)((lane >> 3) & 1) * 16;

    load_chunk(sb,               A, lda, m0, Bh, Bl, ldw, n0, 0, tid);
    if (NCHUNK > 1)
        load_chunk(sb + STAGE_BYTES, A, lda, m0, Bh, Bl, ldw, n0, 1, tid);

    for (int i = 0; i < NCHUNK; i++) {
        if (i >= NCHUNK - 2) cp_wait0(); else cp_wait1();
        __syncthreads();
        uint32_t st = sb + (uint32_t)(i & 1) * STAGE_BYTES;

        #pragma unroll
        for (int ks = 0; ks < 4; ks++) {
            uint32_t act = ((uint32_t)(ks * 32) + achunk) ^ axor;
            uint32_t bct = ((uint32_t)(ks * 32) + bchunk) ^ axor;
            uint32_t ah[4][4], bh[2][4], bl[2][4];
            #pragma unroll
            for (int mi = 0; mi < 4; mi++)
                ldsm4(ah[mi], st + arow + (uint32_t)mi * 2048 + act);
            #pragma unroll
            for (int nj = 0; nj < 2; nj++) {
                uint32_t base = st + 16384 + brow + (uint32_t)nj * 2048 + bct;
                ldsm4(bh[nj], base);
                ldsm4(bl[nj], base + 16384);
            }
            #pragma unroll
            for (int mi = 0; mi < 4; mi++)
                #pragma unroll
                for (int ni = 0; ni < 4; ni++)
                    mma16816(acc[mi][ni], ah[mi], &bh[ni >> 1][(ni & 1) * 2]);
            #pragma unroll
            for (int mi = 0; mi < 4; mi++)
                #pragma unroll
                for (int ni = 0; ni < 4; ni++)
                    mma16816(acc[mi][ni], ah[mi], &bl[ni >> 1][(ni & 1) * 2]);
        }
        __syncthreads();
        if (i + 2 < NCHUNK)
            load_chunk(sb + (uint32_t)(i & 1) * STAGE_BYTES,
                       A, lda, m0, Bh, Bl, ldw, n0, i + 2, tid);
    }

    // epilogue: frags -> padded smem (+bias) -> coalesced stores
    float* epi = (float*)smem;
    int g = lane >> 2, t2 = (lane & 3) * 2;
    #pragma unroll
    for (int mi = 0; mi < 4; mi++) {
        #pragma unroll
        for (int ni = 0; ni < 4; ni++) {
            int r = wm + mi * 16 + g;
            int c = wn + ni * 8 + t2;
            float b0 = bias[n0 + c], b1 = bias[n0 + c + 1];
            epi[r * 132 + c]           = acc[mi][ni][0] + b0;
            epi[r * 132 + c + 1]       = acc[mi][ni][1] + b1;
            epi[(r + 8) * 132 + c]     = acc[mi][ni][2] + b0;
            epi[(r + 8) * 132 + c + 1] = acc[mi][ni][3] + b1;
        }
    }
    __syncthreads();

    if (MODE == 0) {
        #pragma unroll 4
        for (int idx = tid; idx < BM * BN; idx += 256) {
            int r = idx >> 7, c = idx & 127;
            of[(size_t)(m0 + r) * ldc + n0 + c] = epi[r * 132 + c];
        }
    } else {
        int b = m0 >> 11, tb = m0 & (CT - 1);
        #pragma unroll 4
        for (int idx = tid; idx < BM * BN; idx += 256) {
            int n = idx >> 7, tt = idx & 127;
            of[(size_t)b * (CC * CT) + (size_t)(n0 + n) * CT + tb + tt] = epi[tt * 132 + n];
        }
    }
}

// ---------------------------------------------------------------------------
// K3: tiny 2x2 attention (vectorized); CTX fp16 + per-token head-avg probs.
// ---------------------------------------------------------------------------
__global__ void k_attn() {
    __shared__ float sp[2][CH][4];
    int tid = threadIdx.x;
    int local = tid >> 7;
    int token = blockIdx.x * 2 + local;
    int head = (tid >> 5) & 3;
    int lane = tid & 31;

    const float* base0 = g_QKV + (size_t)(2 * token) * (3 * CC);
    const float* base1 = base0 + 3 * CC;
    int col4 = head * CDH + lane * 4;

    float4 q0 = *(const float4*)(base0 + col4);
    float4 k0 = *(const float4*)(base0 + CC + col4);
    float4 v0 = *(const float4*)(base0 + 2 * CC + col4);
    float4 q1 = *(const float4*)(base1 + col4);
    float4 k1 = *(const float4*)(base1 + CC + col4);
    float4 v1 = *(const float4*)(base1 + 2 * CC + col4);

    float s00 = q0.x * k0.x + q0.y * k0.y + q0.z * k0.z + q0.w * k0.w;
    float s01 = q0.x * k1.x + q0.y * k1.y + q0.z * k1.z + q0.w * k1.w;
    float s10 = q1.x * k0.x + q1.y * k0.y + q1.z * k0.z + q1.w * k0.w;
    float s11 = q1.x * k1.x + q1.y * k1.y + q1.z * k1.z + q1.w * k1.w;

    #pragma unroll
    for (int o = 16; o > 0; o >>= 1) {
        s00 += __shfl_xor_sync(0xffffffffu, s00, o);
        s01 += __shfl_xor_sync(0xffffffffu, s01, o);
        s10 += __shfl_xor_sync(0xffffffffu, s10, o);
        s11 += __shfl_xor_sync(0xffffffffu, s11, o);
    }
    const float sc = 0.088388347648318447f;  // 1/sqrt(128)
    s00 *= sc; s01 *= sc; s10 *= sc; s11 *= sc;

    float mx0 = fmaxf(s00, s01);
    float e00 = expf(s00 - mx0), e01 = expf(s01 - mx0);
    float inv0 = 1.f / (e00 + e01);
    float p00 = e00 * inv0, p01 = e01 * inv0;

    float mx1 = fmaxf(s10, s11);
    float e10 = expf(s10 - mx1), e11 = expf(s11 - mx1);
    float inv1 = 1.f / (e10 + e11);
    float p10 = e10 * inv1, p11 = e11 * inv1;

    size_t row0 = (size_t)(2 * token) * CC;
    __half2* d00 = (__half2*)(g_CTX + row0 + col4);
    __half2* d10 = (__half2*)(g_CTX + row0 + CC + col4);
    d00[0] = __floats2half2_rn(p00 * v0.x + p01 * v1.x, p00 * v0.y + p01 * v1.y);
    d00[1] = __floats2half2_rn(p00 * v0.z + p01 * v1.z, p00 * v0.w + p01 * v1.w);
    d10[0] = __floats2half2_rn(p10 * v0.x + p11 * v1.x, p10 * v0.y + p11 * v1.y);
    d10[1] = __floats2half2_rn(p10 * v0.z + p11 * v1.z, p10 * v0.w + p11 * v1.w);

    if (lane == 0) {
        sp[local][head][0] = p00; sp[local][head][1] = p01;
        sp[local][head][2] = p10; sp[local][head][3] = p11;
    }
    __syncthreads();
    if ((tid & 127) < 4) {
        int j = tid & 3;
        float s = (sp[local][0][j] + sp[local][1][j]) +
                  (sp[local][2][j] + sp[local][3][j]);
        g_PATT[(size_t)token * 4 + j] = s * 0.25f;
    }
}

// ---------------------------------------------------------------------------
// K7: avg_attention tail
// ---------------------------------------------------------------------------
__global__ void k_avg(float* __restrict__ out) {
    __shared__ float red[256];
    int b = blockIdx.x;
    for (int j = 0; j < 4; j++) {
        float s = 0.f;
        for (int t = threadIdx.x; t < CT; t += 256)
            s += g_PATT[((size_t)b * CT + t) * 4 + j];
        red[threadIdx.x] = s;
        __syncthreads();
        for (int w = 128; w > 0; w >>= 1) {
            if (threadIdx.x < w) red[threadIdx.x] += red[threadIdx.x + w];
            __syncthreads();
        }
        if (threadIdx.x == 0)
            out[(size_t)CB * CC * CT + b * 4 + j] = red[0] * (1.0f / CT);
        __syncthreads();
    }
}

// ---------------------------------------------------------------------------
// Host launcher (graph-capturable: kernel launches only)
// ---------------------------------------------------------------------------
extern "C" void kernel_launch(void* const* d_in, const int* in_sizes, int n_in,
                              void* d_out, int out_size) {
    const float* x   = (const float*)d_in[0];
    const float* emb = (const float*)d_in[1];
    const float* w1  = (const float*)d_in[2];
    const float* b1  = (const float*)d_in[3];
    const float* wo  = (const float*)d_in[4];
    const float* bo  = (const float*)d_in[5];
    const float* wp  = (const float*)d_in[6];
    const float* bp  = (const float*)d_in[7];
    const float* wim = (const float*)d_in[8];
    const float* bim = (const float*)d_in[9];
    const float* w2  = (const float*)d_in[10];
    const float* b2  = (const float*)d_in[11];
    float* out = (float*)d_out;

    __half *xe, *ctx, *w1h, *w1l, *uh, *ul;
    float *qkv, *s1, *s2, *u, *bt;
    cudaGetSymbolAddress((void**)&xe,  g_XE);
    cudaGetSymbolAddress((void**)&qkv, g_QKV);
    cudaGetSymbolAddress((void**)&ctx, g_CTX);
    cudaGetSymbolAddress((void**)&w1h, g_W1h); cudaGetSymbolAddress((void**)&w1l, g_W1l);
    cudaGetSymbolAddress((void**)&s1,  g_S1);  cudaGetSymbolAddress((void**)&s2,  g_S2);
    cudaGetSymbolAddress((void**)&u,   g_U);
    cudaGetSymbolAddress((void**)&uh,  g_Uh);  cudaGetSymbolAddress((void**)&ul,  g_Ul);
    cudaGetSymbolAddress((void**)&bt,  g_BT);

    cudaFuncSetAttribute(k_tgemm<0, 8>,  cudaFuncAttributeMaxDynamicSharedMemorySize, SMEM_TOTAL);
    cudaFuncSetAttribute(k_tgemm<2, 16>, cudaFuncAttributeMaxDynamicSharedMemorySize, SMEM_TOTAL);

    // --- weight preprocessing ---
    k_cvt<<<(3 * CC * CC + 255) / 256, 256>>>(w1, w1h, w1l, 3 * CC * CC);
    // stage 1: S1 = W2a @ Wp, S2 = W2b @ Wi
    k_snn2<<<dim3(8, 8, 16), 256>>>(w2, 2 * CC, wp, CC, w2 + CC, 2 * CC, wim, CC);
    k_sred2<<<dim3(CC, 2), 256>>>(s1, CC, s2, CC);
    // stage 2: U = [S1 @ Wo | S2 @ Wo]
    k_snn2<<<dim3(8, 8, 16), 256>>>(s1, CC, wo, CC, s2, CC, wo, CC);
    k_sred2<<<dim3(CC, 2), 256>>>(u, 2 * CC, u + CC, 2 * CC);
    k_cvt<<<(CC * 2 * CC + 255) / 256, 256>>>(u, uh, ul, CC * 2 * CC);
    k_bias1<<<4, 128>>>(wp, bp, wim, bim, bo);
    k_bias2<<<4, 128>>>(w2, b2);

    // --- main pipeline ---
    k_embed<<<dim3(CT / 32, CC / 32, CB * 2), dim3(32, 8)>>>(x, emb);

    // GEMM1: QKV (65536 x 1536, K=512) -> fp32
    k_tgemm<0, 8><<<dim3(3 * CC / BN, NROW / BM), 256, SMEM_TOTAL>>>(
        xe, CC, w1h, w1l, CC, b1, qkv, 3 * CC);

    // attention -> ctx fp16 (contiguous (NTOK, 1024) view)
    k_attn<<<NTOK / 2, 256>>>();

    // Fused out_proj+phone/imu+output: (32768 x 512, K=1024), transposed store
    k_tgemm<2, 16><<<dim3(CC / BN, NTOK / BM), 256, SMEM_TOTAL>>>(
        ctx, 2 * CC, uh, ul, 2 * CC, bt, out, 0);

    // avg_attention tail
    k_avg<<<CB, 256>>>(out);
}

// round 12
// speedup vs baseline: 1.9642x; 1.3311x over previous
#include <cuda_runtime.h>
#include <cuda_fp16.h>
#include <cstdint>
#include <math.h>

// Problem constants
#define CB   16
#define CT   2048
#define CC   512
#define CH   4
#define CDH  128
#define NTOK (CB * CT)     // 32768 tokens
#define NROW (NTOK * 2)    // 65536 token-device rows

// GEMM tiling: 128x128 tile, BK=64
#define BM 128
#define BN 128
#define BK 64
// NPROD=1: A 16K | Bh 16K  (stage 32K);  NPROD=2: A | Bh | Bl (stage 48K)
#define SMEM_G1 69632            // max(2*32768, epi 128*132*4=67584) rounded up
#define SMEM_G2 98304            // 2*49152

#define SW128(off) ((off) ^ (((off) >> 3) & 0x70))

// ---------------------------------------------------------------------------
// Scratch (static __device__; no runtime allocation)
// ---------------------------------------------------------------------------
__device__ __half g_XE [(size_t)NROW * CC];           // fp16 activations
__device__ __half g_QKV[(size_t)NROW * 3 * CC];       // fp16 q|k|v
__device__ __half g_CTX[(size_t)NROW * CC];           // viewed as (NTOK, 1024)
__device__ float  g_PATT[(size_t)NTOK * 4];
__device__ __half g_W1h[3 * CC * CC], g_W1l[3 * CC * CC];
// fused-weight pipeline
__device__ float  g_PART[16 * CC * CC];               // split-K partials
__device__ float  g_S1[CC * CC];                      // W2a @ Wp
__device__ float  g_S2[CC * CC];                      // W2b @ Wi
__device__ float  g_U [CC * 2 * CC];                  // [S1@Wo | S2@Wo]
__device__ __half g_Uh[CC * 2 * CC], g_Ul[CC * 2 * CC];
__device__ float  g_BB[2 * CC];
__device__ float  g_BT[CC];

// ---------------------------------------------------------------------------
// Helpers
// ---------------------------------------------------------------------------
__device__ __forceinline__ uint32_t smem_u32(const void* p) {
    uint32_t a;
    asm("{ .reg .u64 t; cvta.to.shared.u64 t, %1; cvt.u32.u64 %0, t; }" : "=r"(a) : "l"(p));
    return a;
}
__device__ __forceinline__ void cp16(uint32_t dst, const void* src) {
    unsigned long long g = (unsigned long long)__cvta_generic_to_global(src);
    asm volatile("cp.async.cg.shared.global [%0], [%1], 16;" :: "r"(dst), "l"(g) : "memory");
}
__device__ __forceinline__ void cp_commit() { asm volatile("cp.async.commit_group;" ::: "memory"); }
__device__ __forceinline__ void cp_wait1()  { asm volatile("cp.async.wait_group 1;" ::: "memory"); }
__device__ __forceinline__ void cp_wait0()  { asm volatile("cp.async.wait_group 0;" ::: "memory"); }

__device__ __forceinline__ void ldsm4(uint32_t* r, uint32_t addr) {
    asm volatile("ldmatrix.sync.aligned.m8n8.x4.shared.b16 {%0,%1,%2,%3}, [%4];"
                 : "=r"(r[0]), "=r"(r[1]), "=r"(r[2]), "=r"(r[3]) : "r"(addr));
}
__device__ __forceinline__ void mma16816(float* d, const uint32_t* a, const uint32_t* b) {
    asm volatile(
        "mma.sync.aligned.m16n8k16.row.col.f32.f16.f16.f32 "
        "{%0,%1,%2,%3}, {%4,%5,%6,%7}, {%8,%9}, {%0,%1,%2,%3};"
        : "+f"(d[0]), "+f"(d[1]), "+f"(d[2]), "+f"(d[3])
        : "r"(a[0]), "r"(a[1]), "r"(a[2]), "r"(a[3]), "r"(b[0]), "r"(b[1]));
}
__device__ __forceinline__ void split2h(float v, __half& h, __half& l) {
    h = __float2half(v);
    l = __float2half(v - __half2float(h));
}
__device__ __forceinline__ float4 ld_half4(const __half* p) {
    __half2 a = *(const __half2*)p;
    __half2 b = *(const __half2*)(p + 2);
    float2 fa = __half22float2(a), fb = __half22float2(b);
    return make_float4(fa.x, fa.y, fb.x, fb.y);
}

// ---------------------------------------------------------------------------
// K0: fp32 -> hi/lo fp16 (weights)
// ---------------------------------------------------------------------------
__global__ void k_cvt(const float* __restrict__ s, __half* __restrict__ h,
                      __half* __restrict__ l, int n) {
    int i = blockIdx.x * 256 + threadIdx.x;
    if (i < n) split2h(s[i], h[i], l[i]);
}

// ---------------------------------------------------------------------------
// Paired split-K fp32 SGEMM (preamble)
// ---------------------------------------------------------------------------
__global__ void __launch_bounds__(256)
k_snn2(const float* __restrict__ A0, int lda0, const float* __restrict__ B0, int ldb0,
       const float* __restrict__ A1, int lda1, const float* __restrict__ B1, int ldb1) {
    __shared__ __align__(16) float As[64][68];
    __shared__ __align__(16) float Bs[64][68];
    int tid = threadIdx.x;
    int p = blockIdx.z >> 3, kz = blockIdx.z & 7;
    const float* A = p ? A1 : A0;  int lda = p ? lda1 : lda0;
    const float* B = p ? B1 : B0;  int ldb = p ? ldb1 : ldb0;
    int n0 = blockIdx.x * 64, m0 = blockIdx.y * 64;
    int k0 = kz * 64;
    int tr = tid / 16, tc = tid % 16;
    int lr = tid / 16, lc4 = (tid % 16) * 4;

    #pragma unroll
    for (int h = 0; h < 4; h++) {
        int r = lr + h * 16;
        float4 a = *(const float4*)(A + (size_t)(m0 + r) * lda + k0 + lc4);
        As[lc4 + 0][r] = a.x; As[lc4 + 1][r] = a.y;
        As[lc4 + 2][r] = a.z; As[lc4 + 3][r] = a.w;
        *(float4*)&Bs[r][lc4] = *(const float4*)(B + (size_t)(k0 + r) * ldb + n0 + lc4);
    }
    __syncthreads();

    float acc[4][4];
    #pragma unroll
    for (int i = 0; i < 4; i++)
        #pragma unroll
        for (int j = 0; j < 4; j++) acc[i][j] = 0.f;

    #pragma unroll 8
    for (int k = 0; k < 64; k++) {
        float4 ra = *(const float4*)&As[k][tr * 4];
        float4 rb = *(const float4*)&Bs[k][tc * 4];
        float a[4] = {ra.x, ra.y, ra.z, ra.w};
        float b[4] = {rb.x, rb.y, rb.z, rb.w};
        #pragma unroll
        for (int i = 0; i < 4; i++)
            #pragma unroll
            for (int j = 0; j < 4; j++)
                acc[i][j] += a[i] * b[j];
    }

    float* part = g_PART + (size_t)blockIdx.z * CC * CC;
    #pragma unroll
    for (int i = 0; i < 4; i++)
        *(float4*)(part + (size_t)(m0 + tr * 4 + i) * CC + n0 + tc * 4) =
            make_float4(acc[i][0], acc[i][1], acc[i][2], acc[i][3]);
}

__global__ void __launch_bounds__(256)
k_sred2(float* __restrict__ d0, int ldc0, float* __restrict__ d1, int ldc1) {
    int p = blockIdx.y;
    float* dst = p ? d1 : d0;
    int ldc = p ? ldc1 : ldc0;
    const float* base = g_PART + (size_t)p * 8 * CC * CC;
    int m = blockIdx.x;
    int n = threadIdx.x * 2;
    #pragma unroll
    for (int q = 0; q < 2; q++) {
        float s = 0.f;
        #pragma unroll
        for (int sl = 0; sl < 8; sl++)
            s += base[(size_t)sl * CC * CC + (size_t)m * CC + n + q];
        dst[(size_t)m * ldc + n + q] = s;
    }
}

// ---------------------------------------------------------------------------
// Bias folding
// ---------------------------------------------------------------------------
__global__ void k_bias1(const float* __restrict__ wp, const float* __restrict__ bp,
                        const float* __restrict__ wi, const float* __restrict__ bi,
                        const float* __restrict__ bo) {
    int i = threadIdx.x + blockIdx.x * 128;
    float s0 = bp[i], s1 = bi[i];
    for (int k = 0; k < CC; k++) {
        float b = bo[k];
        s0 += wp[i * CC + k] * b;
        s1 += wi[i * CC + k] * b;
    }
    g_BB[i] = s0;
    g_BB[CC + i] = s1;
}
__global__ void k_bias2(const float* __restrict__ w2, const float* __restrict__ b2) {
    int n = threadIdx.x + blockIdx.x * 128;
    float s = b2[n];
    for (int a = 0; a < CC; a++)
        s += w2[n * 2 * CC + a] * g_BB[a] + w2[n * 2 * CC + CC + a] * g_BB[CC + a];
    g_BT[n] = s;
}

// ---------------------------------------------------------------------------
// K1: x (B, C, 2, T) -> XE fp16 with device embedding
// ---------------------------------------------------------------------------
__global__ void k_embed(const float* __restrict__ x, const float* __restrict__ emb) {
    __shared__ float s[32][33];
    int t0 = blockIdx.x * 32;
    int c0 = blockIdx.y * 32;
    int bd = blockIdx.z;
    int b = bd >> 1, d = bd & 1;

    #pragma unroll
    for (int j = 0; j < 4; j++) {
        int c = c0 + threadIdx.y + j * 8;
        s[threadIdx.y + j * 8][threadIdx.x] =
            x[(((size_t)b * CC + c) * 2 + d) * CT + t0 + threadIdx.x];
    }
    __syncthreads();
    #pragma unroll
    for (int j = 0; j < 4; j++) {
        int t = t0 + threadIdx.y + j * 8;
        int c = c0 + threadIdx.x;
        float v = s[threadIdx.x][threadIdx.y + j * 8] + emb[d * CC + c];
        g_XE[((size_t)(b * CT + t) * 2 + d) * CC + c] = __float2half(v);
    }
}

// ---------------------------------------------------------------------------
// HMMA GEMM: D[m][n] = bias[n] + sum_k A[m][k]*(Bh[+Bl])[n][k]
// NPROD=1: single fp16 product.  NPROD=2: weight hi/lo 2-product.
// MODE 2: fp32 transposed (B, C, T).  MODE 3: fp16 row-major.
// ---------------------------------------------------------------------------
template <int NPROD>
__device__ __forceinline__ void load_chunk(
    uint32_t sbase,
    const __half* __restrict__ A, int lda, int m0,
    const __half* __restrict__ Bh, const __half* __restrict__ Bl,
    int ldw, int n0, int kc, int tid)
{
    #pragma unroll
    for (int t = 0; t < 4; t++) {
        int id = tid + t * 256;
        int r = id >> 3, j = id & 7;
        uint32_t off = SW128((uint32_t)(r * 128 + j * 16));
        size_t ga = (size_t)(m0 + r) * lda + (size_t)kc * BK + j * 8;
        cp16(sbase + off, A + ga);
        size_t gb = (size_t)(n0 + r) * ldw + (size_t)kc * BK + j * 8;
        cp16(sbase + 16384 + off, Bh + gb);
        if (NPROD == 2) cp16(sbase + 32768 + off, Bl + gb);
    }
    cp_commit();
}

template <int MODE, int NCHUNK, int NPROD>
__global__ void __launch_bounds__(256, 2)
k_tgemm(const __half* __restrict__ A, int lda,
        const __half* __restrict__ Bh, const __half* __restrict__ Bl, int ldw,
        const float* __restrict__ bias,
        float* __restrict__ of, __half* __restrict__ oh, int ldc)
{
    constexpr uint32_t STAGE = (NPROD == 2) ? 49152u : 32768u;
    extern __shared__ __align__(1024) char smem[];
    uint32_t sb = smem_u32(smem);
    int tid = threadIdx.x, lane = tid & 31, wid = tid >> 5;
    int m0 = blockIdx.y * BM, n0 = blockIdx.x * BN;
    int wm = (wid >> 2) * 64, wn = (wid & 3) * 32;

    float acc[4][4][4];
    #pragma unroll
    for (int a = 0; a < 4; a++)
        #pragma unroll
        for (int b = 0; b < 4; b++)
            #pragma unroll
            for (int c = 0; c < 4; c++) acc[a][b][c] = 0.f;

    uint32_t axor   = (uint32_t)(lane & 7) << 4;
    uint32_t arow   = (uint32_t)(wm + (lane & 15)) * 128;
    uint32_t achunk = (uint32_t)(lane >> 4) * 16;
    uint32_t brow   = (uint32_t)(wn + (lane & 7) + ((lane >> 4) << 3)) * 128;
    uint32_t bchunk = (uint32_t)((lane >> 3) & 1) * 16;

    load_chunk<NPROD>(sb,         A, lda, m0, Bh, Bl, ldw, n0, 0, tid);
    if (NCHUNK > 1)
        load_chunk<NPROD>(sb + STAGE, A, lda, m0, Bh, Bl, ldw, n0, 1, tid);

    for (int i = 0; i < NCHUNK; i++) {
        if (i >= NCHUNK - 2) cp_wait0(); else cp_wait1();
        __syncthreads();
        uint32_t st = sb + (uint32_t)(i & 1) * STAGE;

        #pragma unroll
        for (int ks = 0; ks < 4; ks++) {
            uint32_t act = ((uint32_t)(ks * 32) + achunk) ^ axor;
            uint32_t bct = ((uint32_t)(ks * 32) + bchunk) ^ axor;
            uint32_t ah[4][4], bh[2][4], bl[2][4];
            #pragma unroll
            for (int mi = 0; mi < 4; mi++)
                ldsm4(ah[mi], st + arow + (uint32_t)mi * 2048 + act);
            #pragma unroll
            for (int nj = 0; nj < 2; nj++) {
                uint32_t base = st + 16384 + brow + (uint32_t)nj * 2048 + bct;
                ldsm4(bh[nj], base);
                if (NPROD == 2) ldsm4(bl[nj], base + 16384);
            }
            #pragma unroll
            for (int mi = 0; mi < 4; mi++)
                #pragma unroll
                for (int ni = 0; ni < 4; ni++)
                    mma16816(acc[mi][ni], ah[mi], &bh[ni >> 1][(ni & 1) * 2]);
            if (NPROD == 2) {
                #pragma unroll
                for (int mi = 0; mi < 4; mi++)
                    #pragma unroll
                    for (int ni = 0; ni < 4; ni++)
                        mma16816(acc[mi][ni], ah[mi], &bl[ni >> 1][(ni & 1) * 2]);
            }
        }
        __syncthreads();
        if (i + 2 < NCHUNK)
            load_chunk<NPROD>(sb + (uint32_t)(i & 1) * STAGE,
                              A, lda, m0, Bh, Bl, ldw, n0, i + 2, tid);
    }

    // epilogue: frags -> padded smem (+bias) -> coalesced stores
    float* epi = (float*)smem;
    int g = lane >> 2, t2 = (lane & 3) * 2;
    #pragma unroll
    for (int mi = 0; mi < 4; mi++) {
        #pragma unroll
        for (int ni = 0; ni < 4; ni++) {
            int r = wm + mi * 16 + g;
            int c = wn + ni * 8 + t2;
            float b0 = bias[n0 + c], b1 = bias[n0 + c + 1];
            epi[r * 132 + c]           = acc[mi][ni][0] + b0;
            epi[r * 132 + c + 1]       = acc[mi][ni][1] + b1;
            epi[(r + 8) * 132 + c]     = acc[mi][ni][2] + b0;
            epi[(r + 8) * 132 + c + 1] = acc[mi][ni][3] + b1;
        }
    }
    __syncthreads();

    if (MODE == 2) {
        int b = m0 >> 11, tb = m0 & (CT - 1);
        #pragma unroll 4
        for (int idx = tid; idx < BM * BN; idx += 256) {
            int n = idx >> 7, tt = idx & 127;
            of[(size_t)b * (CC * CT) + (size_t)(n0 + n) * CT + tb + tt] = epi[tt * 132 + n];
        }
    } else {  // MODE 3: fp16 row-major, half2 stores
        #pragma unroll 4
        for (int idx = tid; idx < BM * BN / 2; idx += 256) {
            int r = idx / (BN / 2), c = (idx % (BN / 2)) * 2;
            __half2 v = __floats2half2_rn(epi[r * 132 + c], epi[r * 132 + c + 1]);
            *(__half2*)(oh + (size_t)(m0 + r) * ldc + n0 + c) = v;
        }
    }
}

// ---------------------------------------------------------------------------
// K3: tiny 2x2 attention (fp16 QKV in); CTX fp16 + per-token head-avg probs.
// ---------------------------------------------------------------------------
__global__ void k_attn() {
    __shared__ float sp[2][CH][4];
    int tid = threadIdx.x;
    int local = tid >> 7;
    int token = blockIdx.x * 2 + local;
    int head = (tid >> 5) & 3;
    int lane = tid & 31;

    const __half* base0 = g_QKV + (size_t)(2 * token) * (3 * CC);
    const __half* base1 = base0 + 3 * CC;
    int col4 = head * CDH + lane * 4;

    float4 q0 = ld_half4(base0 + col4);
    float4 k0 = ld_half4(base0 + CC + col4);
    float4 v0 = ld_half4(base0 + 2 * CC + col4);
    float4 q1 = ld_half4(base1 + col4);
    float4 k1 = ld_half4(base1 + CC + col4);
    float4 v1 = ld_half4(base1 + 2 * CC + col4);

    float s00 = q0.x * k0.x + q0.y * k0.y + q0.z * k0.z + q0.w * k0.w;
    float s01 = q0.x * k1.x + q0.y * k1.y + q0.z * k1.z + q0.w * k1.w;
    float s10 = q1.x * k0.x + q1.y * k0.y + q1.z * k0.z + q1.w * k0.w;
    float s11 = q1.x * k1.x + q1.y * k1.y + q1.z * k1.z + q1.w * k1.w;

    #pragma unroll
    for (int o = 16; o > 0; o >>= 1) {
        s00 += __shfl_xor_sync(0xffffffffu, s00, o);
        s01 += __shfl_xor_sync(0xffffffffu, s01, o);
        s10 += __shfl_xor_sync(0xffffffffu, s10, o);
        s11 += __shfl_xor_sync(0xffffffffu, s11, o);
    }
    const float sc = 0.088388347648318447f;  // 1/sqrt(128)
    s00 *= sc; s01 *= sc; s10 *= sc; s11 *= sc;

    float mx0 = fmaxf(s00, s01);
    float e00 = expf(s00 - mx0), e01 = expf(s01 - mx0);
    float inv0 = 1.f / (e00 + e01);
    float p00 = e00 * inv0, p01 = e01 * inv0;

    float mx1 = fmaxf(s10, s11);
    float e10 = expf(s10 - mx1), e11 = expf(s11 - mx1);
    float inv1 = 1.f / (e10 + e11);
    float p10 = e10 * inv1, p11 = e11 * inv1;

    size_t row0 = (size_t)(2 * token) * CC;
    __half2* d00 = (__half2*)(g_CTX + row0 + col4);
    __half2* d10 = (__half2*)(g_CTX + row0 + CC + col4);
    d00[0] = __floats2half2_rn(p00 * v0.x + p01 * v1.x, p00 * v0.y + p01 * v1.y);
    d00[1] = __floats2half2_rn(p00 * v0.z + p01 * v1.z, p00 * v0.w + p01 * v1.w);
    d10[0] = __floats2half2_rn(p10 * v0.x + p11 * v1.x, p10 * v0.y + p11 * v1.y);
    d10[1] = __floats2half2_rn(p10 * v0.z + p11 * v1.z, p10 * v0.w + p11 * v1.w);

    if (lane == 0) {
        sp[local][head][0] = p00; sp[local][head][1] = p01;
        sp[local][head][2] = p10; sp[local][head][3] = p11;
    }
    __syncthreads();
    if ((tid & 127) < 4) {
        int j = tid & 3;
        float s = (sp[local][0][j] + sp[local][1][j]) +
                  (sp[local][2][j] + sp[local][3][j]);
        g_PATT[(size_t)token * 4 + j] = s * 0.25f;
    }
}

// ---------------------------------------------------------------------------
// K7: avg_attention tail
// ---------------------------------------------------------------------------
__global__ void k_avg(float* __restrict__ out) {
    __shared__ float red[256];
    int b = blockIdx.x;
    for (int j = 0; j < 4; j++) {
        float s = 0.f;
        for (int t = threadIdx.x; t < CT; t += 256)
            s += g_PATT[((size_t)b * CT + t) * 4 + j];
        red[threadIdx.x] = s;
        __syncthreads();
        for (int w = 128; w > 0; w >>= 1) {
            if (threadIdx.x < w) red[threadIdx.x] += red[threadIdx.x + w];
            __syncthreads();
        }
        if (threadIdx.x == 0)
            out[(size_t)CB * CC * CT + b * 4 + j] = red[0] * (1.0f / CT);
        __syncthreads();
    }
}

// ---------------------------------------------------------------------------
// Host launcher (graph-capturable: kernel launches only)
// ---------------------------------------------------------------------------
extern "C" void kernel_launch(void* const* d_in, const int* in_sizes, int n_in,
                              void* d_out, int out_size) {
    const float* x   = (const float*)d_in[0];
    const float* emb = (const float*)d_in[1];
    const float* w1  = (const float*)d_in[2];
    const float* b1  = (const float*)d_in[3];
    const float* wo  = (const float*)d_in[4];
    const float* bo  = (const float*)d_in[5];
    const float* wp  = (const float*)d_in[6];
    const float* bp  = (const float*)d_in[7];
    const float* wim = (const float*)d_in[8];
    const float* bim = (const float*)d_in[9];
    const float* w2  = (const float*)d_in[10];
    const float* b2  = (const float*)d_in[11];
    float* out = (float*)d_out;

    __half *xe, *qkv, *ctx, *w1h, *w1l, *uh, *ul;
    float *s1, *s2, *u, *bt;
    cudaGetSymbolAddress((void**)&xe,  g_XE);
    cudaGetSymbolAddress((void**)&qkv, g_QKV);
    cudaGetSymbolAddress((void**)&ctx, g_CTX);
    cudaGetSymbolAddress((void**)&w1h, g_W1h); cudaGetSymbolAddress((void**)&w1l, g_W1l);
    cudaGetSymbolAddress((void**)&s1,  g_S1);  cudaGetSymbolAddress((void**)&s2,  g_S2);
    cudaGetSymbolAddress((void**)&u,   g_U);
    cudaGetSymbolAddress((void**)&uh,  g_Uh);  cudaGetSymbolAddress((void**)&ul,  g_Ul);
    cudaGetSymbolAddress((void**)&bt,  g_BT);

    cudaFuncSetAttribute(k_tgemm<3, 8, 1>,  cudaFuncAttributeMaxDynamicSharedMemorySize, SMEM_G1);
    cudaFuncSetAttribute(k_tgemm<2, 16, 2>, cudaFuncAttributeMaxDynamicSharedMemorySize, SMEM_G2);

    // --- weight preprocessing ---
    k_cvt<<<(3 * CC * CC + 255) / 256, 256>>>(w1, w1h, w1l, 3 * CC * CC);
    // stage 1: S1 = W2a @ Wp, S2 = W2b @ Wi
    k_snn2<<<dim3(8, 8, 16), 256>>>(w2, 2 * CC, wp, CC, w2 + CC, 2 * CC, wim, CC);
    k_sred2<<<dim3(CC, 2), 256>>>(s1, CC, s2, CC);
    // stage 2: U = [S1 @ Wo | S2 @ Wo]
    k_snn2<<<dim3(8, 8, 16), 256>>>(s1, CC, wo, CC, s2, CC, wo, CC);
    k_sred2<<<dim3(CC, 2), 256>>>(u, 2 * CC, u + CC, 2 * CC);
    k_cvt<<<(CC * 2 * CC + 255) / 256, 256>>>(u, uh, ul, CC * 2 * CC);
    k_bias1<<<4, 128>>>(wp, bp, wim, bim, bo);
    k_bias2<<<4, 128>>>(w2, b2);

    // --- main pipeline ---
    k_embed<<<dim3(CT / 32, CC / 32, CB * 2), dim3(32, 8)>>>(x, emb);

    // GEMM1: QKV (65536 x 1536, K=512), single-product, fp16 out
    k_tgemm<3, 8, 1><<<dim3(3 * CC / BN, NROW / BM), 256, SMEM_G1>>>(
        xe, CC, w1h, w1l, CC, b1, nullptr, qkv, 3 * CC);

    // attention -> ctx fp16 (contiguous (NTOK, 1024) view)
    k_attn<<<NTOK / 2, 256>>>();

    // Fused out_proj+phone/imu+output: (32768 x 512, K=1024), 2-product,
    // transposed fp32 store
    k_tgemm<2, 16, 2><<<dim3(CC / BN, NTOK / BM), 256, SMEM_G2>>>(
        ctx, 2 * CC, uh, ul, 2 * CC, bt, out, nullptr, 0);

    // avg_attention tail
    k_avg<<<CB, 256>>>(out);
}

// round 13
// speedup vs baseline: 2.1313x; 1.0850x over previous
#include <cuda_runtime.h>
#include <cuda_fp16.h>
#include <cstdint>
#include <math.h>

// Problem constants
#define CB   16
#define CT   2048
#define CC   512
#define CH   4
#define CDH  128
#define NTOK (CB * CT)     // 32768 tokens
#define NROW (NTOK * 2)    // 65536 token-device rows

// GEMM tiling: 128x128 tile, BK=64, single fp16 product (both GEMMs)
#define BM 128
#define BN 128
#define BK 64
#define SMEM_G 69632             // max(2 stages * 32K, epi 128*132*4 = 67584)

#define SW128(off) ((off) ^ (((off) >> 3) & 0x70))

// ---------------------------------------------------------------------------
// Scratch (static __device__; no runtime allocation)
// ---------------------------------------------------------------------------
__device__ __half g_XE [(size_t)NROW * CC];           // fp16 activations
__device__ __half g_QKV[(size_t)NROW * 3 * CC];       // fp16 q|k|v
__device__ __half g_CTX[(size_t)NROW * CC];           // viewed as (NTOK, 1024)
__device__ float  g_PATT[(size_t)NTOK * 4];
__device__ __half g_W1h[3 * CC * CC], g_W1l[3 * CC * CC];
// fused-weight pipeline
__device__ float  g_PART[16 * CC * CC];               // split-K partials
__device__ float  g_S1[CC * CC];                      // W2a @ Wp
__device__ float  g_S2[CC * CC];                      // W2b @ Wi
__device__ float  g_U [CC * 2 * CC];                  // [S1@Wo | S2@Wo]
__device__ __half g_Uh[CC * 2 * CC], g_Ul[CC * 2 * CC];
__device__ float  g_BB[2 * CC];
__device__ float  g_BT[CC];

// ---------------------------------------------------------------------------
// Helpers
// ---------------------------------------------------------------------------
__device__ __forceinline__ uint32_t smem_u32(const void* p) {
    uint32_t a;
    asm("{ .reg .u64 t; cvta.to.shared.u64 t, %1; cvt.u32.u64 %0, t; }" : "=r"(a) : "l"(p));
    return a;
}
__device__ __forceinline__ void cp16(uint32_t dst, const void* src) {
    unsigned long long g = (unsigned long long)__cvta_generic_to_global(src);
    asm volatile("cp.async.cg.shared.global [%0], [%1], 16;" :: "r"(dst), "l"(g) : "memory");
}
__device__ __forceinline__ void cp_commit() { asm volatile("cp.async.commit_group;" ::: "memory"); }
__device__ __forceinline__ void cp_wait1()  { asm volatile("cp.async.wait_group 1;" ::: "memory"); }
__device__ __forceinline__ void cp_wait0()  { asm volatile("cp.async.wait_group 0;" ::: "memory"); }

__device__ __forceinline__ void ldsm4(uint32_t* r, uint32_t addr) {
    asm volatile("ldmatrix.sync.aligned.m8n8.x4.shared.b16 {%0,%1,%2,%3}, [%4];"
                 : "=r"(r[0]), "=r"(r[1]), "=r"(r[2]), "=r"(r[3]) : "r"(addr));
}
__device__ __forceinline__ void mma16816(float* d, const uint32_t* a, const uint32_t* b) {
    asm volatile(
        "mma.sync.aligned.m16n8k16.row.col.f32.f16.f16.f32 "
        "{%0,%1,%2,%3}, {%4,%5,%6,%7}, {%8,%9}, {%0,%1,%2,%3};"
        : "+f"(d[0]), "+f"(d[1]), "+f"(d[2]), "+f"(d[3])
        : "r"(a[0]), "r"(a[1]), "r"(a[2]), "r"(a[3]), "r"(b[0]), "r"(b[1]));
}
__device__ __forceinline__ void split2h(float v, __half& h, __half& l) {
    h = __float2half(v);
    l = __float2half(v - __half2float(h));
}
__device__ __forceinline__ float4 ld_half4(const __half* p) {
    __half2 a = *(const __half2*)p;
    __half2 b = *(const __half2*)(p + 2);
    float2 fa = __half22float2(a), fb = __half22float2(b);
    return make_float4(fa.x, fa.y, fb.x, fb.y);
}

// ---------------------------------------------------------------------------
// K0: fp32 -> hi/lo fp16 (weights)
// ---------------------------------------------------------------------------
__global__ void k_cvt(const float* __restrict__ s, __half* __restrict__ h,
                      __half* __restrict__ l, int n) {
    int i = blockIdx.x * 256 + threadIdx.x;
    if (i < n) split2h(s[i], h[i], l[i]);
}

// ---------------------------------------------------------------------------
// Paired split-K fp32 SGEMM (preamble)
// ---------------------------------------------------------------------------
__global__ void __launch_bounds__(256)
k_snn2(const float* __restrict__ A0, int lda0, const float* __restrict__ B0, int ldb0,
       const float* __restrict__ A1, int lda1, const float* __restrict__ B1, int ldb1) {
    __shared__ __align__(16) float As[64][68];
    __shared__ __align__(16) float Bs[64][68];
    int tid = threadIdx.x;
    int p = blockIdx.z >> 3, kz = blockIdx.z & 7;
    const float* A = p ? A1 : A0;  int lda = p ? lda1 : lda0;
    const float* B = p ? B1 : B0;  int ldb = p ? ldb1 : ldb0;
    int n0 = blockIdx.x * 64, m0 = blockIdx.y * 64;
    int k0 = kz * 64;
    int tr = tid / 16, tc = tid % 16;
    int lr = tid / 16, lc4 = (tid % 16) * 4;

    #pragma unroll
    for (int h = 0; h < 4; h++) {
        int r = lr + h * 16;
        float4 a = *(const float4*)(A + (size_t)(m0 + r) * lda + k0 + lc4);
        As[lc4 + 0][r] = a.x; As[lc4 + 1][r] = a.y;
        As[lc4 + 2][r] = a.z; As[lc4 + 3][r] = a.w;
        *(float4*)&Bs[r][lc4] = *(const float4*)(B + (size_t)(k0 + r) * ldb + n0 + lc4);
    }
    __syncthreads();

    float acc[4][4];
    #pragma unroll
    for (int i = 0; i < 4; i++)
        #pragma unroll
        for (int j = 0; j < 4; j++) acc[i][j] = 0.f;

    #pragma unroll 8
    for (int k = 0; k < 64; k++) {
        float4 ra = *(const float4*)&As[k][tr * 4];
        float4 rb = *(const float4*)&Bs[k][tc * 4];
        float a[4] = {ra.x, ra.y, ra.z, ra.w};
        float b[4] = {rb.x, rb.y, rb.z, rb.w};
        #pragma unroll
        for (int i = 0; i < 4; i++)
            #pragma unroll
            for (int j = 0; j < 4; j++)
                acc[i][j] += a[i] * b[j];
    }

    float* part = g_PART + (size_t)blockIdx.z * CC * CC;
    #pragma unroll
    for (int i = 0; i < 4; i++)
        *(float4*)(part + (size_t)(m0 + tr * 4 + i) * CC + n0 + tc * 4) =
            make_float4(acc[i][0], acc[i][1], acc[i][2], acc[i][3]);
}

__global__ void __launch_bounds__(256)
k_sred2(float* __restrict__ d0, int ldc0, float* __restrict__ d1, int ldc1) {
    int p = blockIdx.y;
    float* dst = p ? d1 : d0;
    int ldc = p ? ldc1 : ldc0;
    const float* base = g_PART + (size_t)p * 8 * CC * CC;
    int m = blockIdx.x;
    int n = threadIdx.x * 2;
    #pragma unroll
    for (int q = 0; q < 2; q++) {
        float s = 0.f;
        #pragma unroll
        for (int sl = 0; sl < 8; sl++)
            s += base[(size_t)sl * CC * CC + (size_t)m * CC + n + q];
        dst[(size_t)m * ldc + n + q] = s;
    }
}

// ---------------------------------------------------------------------------
// Bias folding
// ---------------------------------------------------------------------------
__global__ void k_bias1(const float* __restrict__ wp, const float* __restrict__ bp,
                        const float* __restrict__ wi, const float* __restrict__ bi,
                        const float* __restrict__ bo) {
    int i = threadIdx.x + blockIdx.x * 128;
    float s0 = bp[i], s1 = bi[i];
    for (int k = 0; k < CC; k++) {
        float b = bo[k];
        s0 += wp[i * CC + k] * b;
        s1 += wi[i * CC + k] * b;
    }
    g_BB[i] = s0;
    g_BB[CC + i] = s1;
}
__global__ void k_bias2(const float* __restrict__ w2, const float* __restrict__ b2) {
    int n = threadIdx.x + blockIdx.x * 128;
    float s = b2[n];
    for (int a = 0; a < CC; a++)
        s += w2[n * 2 * CC + a] * g_BB[a] + w2[n * 2 * CC + CC + a] * g_BB[CC + a];
    g_BT[n] = s;
}

// ---------------------------------------------------------------------------
// K1: x (B, C, 2, T) -> XE fp16 with device embedding
// ---------------------------------------------------------------------------
__global__ void k_embed(const float* __restrict__ x, const float* __restrict__ emb) {
    __shared__ float s[32][33];
    int t0 = blockIdx.x * 32;
    int c0 = blockIdx.y * 32;
    int bd = blockIdx.z;
    int b = bd >> 1, d = bd & 1;

    #pragma unroll
    for (int j = 0; j < 4; j++) {
        int c = c0 + threadIdx.y + j * 8;
        s[threadIdx.y + j * 8][threadIdx.x] =
            x[(((size_t)b * CC + c) * 2 + d) * CT + t0 + threadIdx.x];
    }
    __syncthreads();
    #pragma unroll
    for (int j = 0; j < 4; j++) {
        int t = t0 + threadIdx.y + j * 8;
        int c = c0 + threadIdx.x;
        float v = s[threadIdx.x][threadIdx.y + j * 8] + emb[d * CC + c];
        g_XE[((size_t)(b * CT + t) * 2 + d) * CC + c] = __float2half(v);
    }
}

// ---------------------------------------------------------------------------
// HMMA GEMM, single fp16 product: D[m][n] = bias[n] + sum_k A[m][k]*B[n][k]
// MODE 2: fp32 transposed (B, C, T).  MODE 3: fp16 row-major.
// ---------------------------------------------------------------------------
__device__ __forceinline__ void load_chunk(
    uint32_t sbase,
    const __half* __restrict__ A, int lda, int m0,
    const __half* __restrict__ Bh, int ldw, int n0, int kc, int tid)
{
    #pragma unroll
    for (int t = 0; t < 4; t++) {
        int id = tid + t * 256;
        int r = id >> 3, j = id & 7;
        uint32_t off = SW128((uint32_t)(r * 128 + j * 16));
        size_t ga = (size_t)(m0 + r) * lda + (size_t)kc * BK + j * 8;
        cp16(sbase + off, A + ga);
        size_t gb = (size_t)(n0 + r) * ldw + (size_t)kc * BK + j * 8;
        cp16(sbase + 16384 + off, Bh + gb);
    }
    cp_commit();
}

template <int MODE, int NCHUNK>
__global__ void __launch_bounds__(256, 2)
k_tgemm(const __half* __restrict__ A, int lda,
        const __half* __restrict__ Bh, int ldw,
        const float* __restrict__ bias,
        float* __restrict__ of, __half* __restrict__ oh, int ldc)
{
    constexpr uint32_t STAGE = 32768u;
    extern __shared__ __align__(1024) char smem[];
    uint32_t sb = smem_u32(smem);
    int tid = threadIdx.x, lane = tid & 31, wid = tid >> 5;
    int m0 = blockIdx.y * BM, n0 = blockIdx.x * BN;
    int wm = (wid >> 2) * 64, wn = (wid & 3) * 32;

    float acc[4][4][4];
    #pragma unroll
    for (int a = 0; a < 4; a++)
        #pragma unroll
        for (int b = 0; b < 4; b++)
            #pragma unroll
            for (int c = 0; c < 4; c++) acc[a][b][c] = 0.f;

    uint32_t axor   = (uint32_t)(lane & 7) << 4;
    uint32_t arow   = (uint32_t)(wm + (lane & 15)) * 128;
    uint32_t achunk = (uint32_t)(lane >> 4) * 16;
    uint32_t brow   = (uint32_t)(wn + (lane & 7) + ((lane >> 4) << 3)) * 128;
    uint32_t bchunk = (uint32_t)((lane >> 3) & 1) * 16;

    load_chunk(sb,         A, lda, m0, Bh, ldw, n0, 0, tid);
    if (NCHUNK > 1)
        load_chunk(sb + STAGE, A, lda, m0, Bh, ldw, n0, 1, tid);

    for (int i = 0; i < NCHUNK; i++) {
        if (i >= NCHUNK - 2) cp_wait0(); else cp_wait1();
        __syncthreads();
        uint32_t st = sb + (uint32_t)(i & 1) * STAGE;

        #pragma unroll
        for (int ks = 0; ks < 4; ks++) {
            uint32_t act = ((uint32_t)(ks * 32) + achunk) ^ axor;
            uint32_t bct = ((uint32_t)(ks * 32) + bchunk) ^ axor;
            uint32_t ah[4][4], bh[2][4];
            #pragma unroll
            for (int mi = 0; mi < 4; mi++)
                ldsm4(ah[mi], st + arow + (uint32_t)mi * 2048 + act);
            #pragma unroll
            for (int nj = 0; nj < 2; nj++)
                ldsm4(bh[nj], st + 16384 + brow + (uint32_t)nj * 2048 + bct);
            #pragma unroll
            for (int mi = 0; mi < 4; mi++)
                #pragma unroll
                for (int ni = 0; ni < 4; ni++)
                    mma16816(acc[mi][ni], ah[mi], &bh[ni >> 1][(ni & 1) * 2]);
        }
        __syncthreads();
        if (i + 2 < NCHUNK)
            load_chunk(sb + (uint32_t)(i & 1) * STAGE,
                       A, lda, m0, Bh, ldw, n0, i + 2, tid);
    }

    // epilogue: frags -> padded smem (+bias) -> coalesced stores
    float* epi = (float*)smem;
    int g = lane >> 2, t2 = (lane & 3) * 2;
    #pragma unroll
    for (int mi = 0; mi < 4; mi++) {
        #pragma unroll
        for (int ni = 0; ni < 4; ni++) {
            int r = wm + mi * 16 + g;
            int c = wn + ni * 8 + t2;
            float b0 = bias[n0 + c], b1 = bias[n0 + c + 1];
            epi[r * 132 + c]           = acc[mi][ni][0] + b0;
            epi[r * 132 + c + 1]       = acc[mi][ni][1] + b1;
            epi[(r + 8) * 132 + c]     = acc[mi][ni][2] + b0;
            epi[(r + 8) * 132 + c + 1] = acc[mi][ni][3] + b1;
        }
    }
    __syncthreads();

    if (MODE == 2) {
        int b = m0 >> 11, tb = m0 & (CT - 1);
        #pragma unroll 4
        for (int idx = tid; idx < BM * BN; idx += 256) {
            int n = idx >> 7, tt = idx & 127;
            of[(size_t)b * (CC * CT) + (size_t)(n0 + n) * CT + tb + tt] = epi[tt * 132 + n];
        }
    } else {  // MODE 3: fp16 row-major, half2 stores
        #pragma unroll 4
        for (int idx = tid; idx < BM * BN / 2; idx += 256) {
            int r = idx / (BN / 2), c = (idx % (BN / 2)) * 2;
            __half2 v = __floats2half2_rn(epi[r * 132 + c], epi[r * 132 + c + 1]);
            *(__half2*)(oh + (size_t)(m0 + r) * ldc + n0 + c) = v;
        }
    }
}

// ---------------------------------------------------------------------------
// K3: tiny 2x2 attention (fp16 QKV in); CTX fp16 + per-token head-avg probs.
// ---------------------------------------------------------------------------
__global__ void k_attn() {
    __shared__ float sp[2][CH][4];
    int tid = threadIdx.x;
    int local = tid >> 7;
    int token = blockIdx.x * 2 + local;
    int head = (tid >> 5) & 3;
    int lane = tid & 31;

    const __half* base0 = g_QKV + (size_t)(2 * token) * (3 * CC);
    const __half* base1 = base0 + 3 * CC;
    int col4 = head * CDH + lane * 4;

    float4 q0 = ld_half4(base0 + col4);
    float4 k0 = ld_half4(base0 + CC + col4);
    float4 v0 = ld_half4(base0 + 2 * CC + col4);
    float4 q1 = ld_half4(base1 + col4);
    float4 k1 = ld_half4(base1 + CC + col4);
    float4 v1 = ld_half4(base1 + 2 * CC + col4);

    float s00 = q0.x * k0.x + q0.y * k0.y + q0.z * k0.z + q0.w * k0.w;
    float s01 = q0.x * k1.x + q0.y * k1.y + q0.z * k1.z + q0.w * k1.w;
    float s10 = q1.x * k0.x + q1.y * k0.y + q1.z * k0.z + q1.w * k0.w;
    float s11 = q1.x * k1.x + q1.y * k1.y + q1.z * k1.z + q1.w * k1.w;

    #pragma unroll
    for (int o = 16; o > 0; o >>= 1) {
        s00 += __shfl_xor_sync(0xffffffffu, s00, o);
        s01 += __shfl_xor_sync(0xffffffffu, s01, o);
        s10 += __shfl_xor_sync(0xffffffffu, s10, o);
        s11 += __shfl_xor_sync(0xffffffffu, s11, o);
    }
    const float sc = 0.088388347648318447f;  // 1/sqrt(128)
    s00 *= sc; s01 *= sc; s10 *= sc; s11 *= sc;

    float mx0 = fmaxf(s00, s01);
    float e00 = expf(s00 - mx0), e01 = expf(s01 - mx0);
    float inv0 = 1.f / (e00 + e01);
    float p00 = e00 * inv0, p01 = e01 * inv0;

    float mx1 = fmaxf(s10, s11);
    float e10 = expf(s10 - mx1), e11 = expf(s11 - mx1);
    float inv1 = 1.f / (e10 + e11);
    float p10 = e10 * inv1, p11 = e11 * inv1;

    size_t row0 = (size_t)(2 * token) * CC;
    __half2* d00 = (__half2*)(g_CTX + row0 + col4);
    __half2* d10 = (__half2*)(g_CTX + row0 + CC + col4);
    d00[0] = __floats2half2_rn(p00 * v0.x + p01 * v1.x, p00 * v0.y + p01 * v1.y);
    d00[1] = __floats2half2_rn(p00 * v0.z + p01 * v1.z, p00 * v0.w + p01 * v1.w);
    d10[0] = __floats2half2_rn(p10 * v0.x + p11 * v1.x, p10 * v0.y + p11 * v1.y);
    d10[1] = __floats2half2_rn(p10 * v0.z + p11 * v1.z, p10 * v0.w + p11 * v1.w);

    if (lane == 0) {
        sp[local][head][0] = p00; sp[local][head][1] = p01;
        sp[local][head][2] = p10; sp[local][head][3] = p11;
    }
    __syncthreads();
    if ((tid & 127) < 4) {
        int j = tid & 3;
        float s = (sp[local][0][j] + sp[local][1][j]) +
                  (sp[local][2][j] + sp[local][3][j]);
        g_PATT[(size_t)token * 4 + j] = s * 0.25f;
    }
}

// ---------------------------------------------------------------------------
// K7: avg_attention tail
// ---------------------------------------------------------------------------
__global__ void k_avg(float* __restrict__ out) {
    __shared__ float red[256];
    int b = blockIdx.x;
    for (int j = 0; j < 4; j++) {
        float s = 0.f;
        for (int t = threadIdx.x; t < CT; t += 256)
            s += g_PATT[((size_t)b * CT + t) * 4 + j];
        red[threadIdx.x] = s;
        __syncthreads();
        for (int w = 128; w > 0; w >>= 1) {
            if (threadIdx.x < w) red[threadIdx.x] += red[threadIdx.x + w];
            __syncthreads();
        }
        if (threadIdx.x == 0)
            out[(size_t)CB * CC * CT + b * 4 + j] = red[0] * (1.0f / CT);
        __syncthreads();
    }
}

// ---------------------------------------------------------------------------
// Host launcher (graph-capturable: kernel launches only)
// ---------------------------------------------------------------------------
extern "C" void kernel_launch(void* const* d_in, const int* in_sizes, int n_in,
                              void* d_out, int out_size) {
    const float* x   = (const float*)d_in[0];
    const float* emb = (const float*)d_in[1];
    const float* w1  = (const float*)d_in[2];
    const float* b1  = (const float*)d_in[3];
    const float* wo  = (const float*)d_in[4];
    const float* bo  = (const float*)d_in[5];
    const float* wp  = (const float*)d_in[6];
    const float* bp  = (const float*)d_in[7];
    const float* wim = (const float*)d_in[8];
    const float* bim = (const float*)d_in[9];
    const float* w2  = (const float*)d_in[10];
    const float* b2  = (const float*)d_in[11];
    float* out = (float*)d_out;

    __half *xe, *qkv, *ctx, *w1h, *w1l, *uh, *ul;
    float *s1, *s2, *u, *bt;
    cudaGetSymbolAddress((void**)&xe,  g_XE);
    cudaGetSymbolAddress((void**)&qkv, g_QKV);
    cudaGetSymbolAddress((void**)&ctx, g_CTX);
    cudaGetSymbolAddress((void**)&w1h, g_W1h); cudaGetSymbolAddress((void**)&w1l, g_W1l);
    cudaGetSymbolAddress((void**)&s1,  g_S1);  cudaGetSymbolAddress((void**)&s2,  g_S2);
    cudaGetSymbolAddress((void**)&u,   g_U);
    cudaGetSymbolAddress((void**)&uh,  g_Uh);  cudaGetSymbolAddress((void**)&ul,  g_Ul);
    cudaGetSymbolAddress((void**)&bt,  g_BT);

    cudaFuncSetAttribute(k_tgemm<3, 8>,  cudaFuncAttributeMaxDynamicSharedMemorySize, SMEM_G);
    cudaFuncSetAttribute(k_tgemm<2, 16>, cudaFuncAttributeMaxDynamicSharedMemorySize, SMEM_G);

    // --- weight preprocessing ---
    k_cvt<<<(3 * CC * CC + 255) / 256, 256>>>(w1, w1h, w1l, 3 * CC * CC);
    // stage 1: S1 = W2a @ Wp, S2 = W2b @ Wi
    k_snn2<<<dim3(8, 8, 16), 256>>>(w2, 2 * CC, wp, CC, w2 + CC, 2 * CC, wim, CC);
    k_sred2<<<dim3(CC, 2), 256>>>(s1, CC, s2, CC);
    // stage 2: U = [S1 @ Wo | S2 @ Wo]
    k_snn2<<<dim3(8, 8, 16), 256>>>(s1, CC, wo, CC, s2, CC, wo, CC);
    k_sred2<<<dim3(CC, 2), 256>>>(u, 2 * CC, u + CC, 2 * CC);
    k_cvt<<<(CC * 2 * CC + 255) / 256, 256>>>(u, uh, ul, CC * 2 * CC);
    k_bias1<<<4, 128>>>(wp, bp, wim, bim, bo);
    k_bias2<<<4, 128>>>(w2, b2);

    // --- main pipeline ---
    k_embed<<<dim3(CT / 32, CC / 32, CB * 2), dim3(32, 8)>>>(x, emb);

    // GEMM1: QKV (65536 x 1536, K=512), single-product, fp16 out
    k_tgemm<3, 8><<<dim3(3 * CC / BN, NROW / BM), 256, SMEM_G>>>(
        xe, CC, w1h, CC, b1, nullptr, qkv, 3 * CC);

    // attention -> ctx fp16 (contiguous (NTOK, 1024) view)
    k_attn<<<NTOK / 2, 256>>>();

    // Fused out_proj+phone/imu+output: (32768 x 512, K=1024),
    // single-product, transposed fp32 store
    k_tgemm<2, 16><<<dim3(CC / BN, NTOK / BM), 256, SMEM_G>>>(
        ctx, 2 * CC, uh, 2 * CC, bt, out, nullptr, 0);

    // avg_attention tail
    k_avg<<<CB, 256>>>(out);
}

// round 14
// speedup vs baseline: 2.1726x; 1.0194x over previous
#include <cuda_runtime.h>
#include <cuda_fp16.h>
#include <cstdint>
#include <math.h>

// Problem constants
#define CB   16
#define CT   2048
#define CC   512
#define CH   4
#define CDH  128
#define NTOK (CB * CT)     // 32768 tokens
#define NROW (NTOK * 2)    // 65536 token-device rows

// GEMM tiling: 128x128 tile, BK=64, single fp16 product, 3-stage pipeline
#define BM 128
#define BN 128
#define BK 64
#define STAGE 32768u
#define SMEM_G 98304             // 3 stages * 32K (>= epi 128*132*4 = 67584)

#define SW128(off) ((off) ^ (((off) >> 3) & 0x70))

// ---------------------------------------------------------------------------
// Scratch (static __device__; no runtime allocation)
// ---------------------------------------------------------------------------
__device__ __half g_XE [(size_t)NROW * CC];           // fp16 activations
__device__ __half g_QKV[(size_t)NROW * 3 * CC];       // fp16 q|k|v
__device__ __half g_CTX[(size_t)NROW * CC];           // viewed as (NTOK, 1024)
__device__ float  g_PATT[(size_t)NTOK * 4];
__device__ __half g_W1h[3 * CC * CC], g_W1l[3 * CC * CC];
// fused-weight pipeline
__device__ float  g_PART[16 * CC * CC];               // split-K partials
__device__ float  g_S1[CC * CC];                      // W2a @ Wp
__device__ float  g_S2[CC * CC];                      // W2b @ Wi
__device__ float  g_U [CC * 2 * CC];                  // [S1@Wo | S2@Wo]
__device__ __half g_Uh[CC * 2 * CC], g_Ul[CC * 2 * CC];
__device__ float  g_BB[2 * CC];
__device__ float  g_BT[CC];

// ---------------------------------------------------------------------------
// Helpers
// ---------------------------------------------------------------------------
__device__ __forceinline__ uint32_t smem_u32(const void* p) {
    uint32_t a;
    asm("{ .reg .u64 t; cvta.to.shared.u64 t, %1; cvt.u32.u64 %0, t; }" : "=r"(a) : "l"(p));
    return a;
}
__device__ __forceinline__ void cp16(uint32_t dst, const void* src) {
    unsigned long long g = (unsigned long long)__cvta_generic_to_global(src);
    asm volatile("cp.async.cg.shared.global [%0], [%1], 16;" :: "r"(dst), "l"(g) : "memory");
}
__device__ __forceinline__ void cp_commit() { asm volatile("cp.async.commit_group;" ::: "memory"); }
__device__ __forceinline__ void cp_wait2()  { asm volatile("cp.async.wait_group 2;" ::: "memory"); }
__device__ __forceinline__ void cp_wait1()  { asm volatile("cp.async.wait_group 1;" ::: "memory"); }
__device__ __forceinline__ void cp_wait0()  { asm volatile("cp.async.wait_group 0;" ::: "memory"); }

__device__ __forceinline__ void ldsm4(uint32_t* r, uint32_t addr) {
    asm volatile("ldmatrix.sync.aligned.m8n8.x4.shared.b16 {%0,%1,%2,%3}, [%4];"
                 : "=r"(r[0]), "=r"(r[1]), "=r"(r[2]), "=r"(r[3]) : "r"(addr));
}
__device__ __forceinline__ void mma16816(float* d, const uint32_t* a, const uint32_t* b) {
    asm volatile(
        "mma.sync.aligned.m16n8k16.row.col.f32.f16.f16.f32 "
        "{%0,%1,%2,%3}, {%4,%5,%6,%7}, {%8,%9}, {%0,%1,%2,%3};"
        : "+f"(d[0]), "+f"(d[1]), "+f"(d[2]), "+f"(d[3])
        : "r"(a[0]), "r"(a[1]), "r"(a[2]), "r"(a[3]), "r"(b[0]), "r"(b[1]));
}
__device__ __forceinline__ void split2h(float v, __half& h, __half& l) {
    h = __float2half(v);
    l = __float2half(v - __half2float(h));
}
__device__ __forceinline__ float4 ld_half4(const __half* p) {
    __half2 a = *(const __half2*)p;
    __half2 b = *(const __half2*)(p + 2);
    float2 fa = __half22float2(a), fb = __half22float2(b);
    return make_float4(fa.x, fa.y, fb.x, fb.y);
}

// ---------------------------------------------------------------------------
// K0: fp32 -> hi/lo fp16 (weights)
// ---------------------------------------------------------------------------
__global__ void k_cvt(const float* __restrict__ s, __half* __restrict__ h,
                      __half* __restrict__ l, int n) {
    int i = blockIdx.x * 256 + threadIdx.x;
    if (i < n) split2h(s[i], h[i], l[i]);
}

// ---------------------------------------------------------------------------
// Paired split-K fp32 SGEMM (preamble). 64x64 tile, 8x4 register tile,
// 128 threads. grid (8, 8, 16): z>>3 selects product, z&7 the K-slice.
// ---------------------------------------------------------------------------
__global__ void __launch_bounds__(128)
k_snn2(const float* __restrict__ A0, int lda0, const float* __restrict__ B0, int ldb0,
       const float* __restrict__ A1, int lda1, const float* __restrict__ B1, int ldb1) {
    __shared__ __align__(16) float As[64][68];
    __shared__ __align__(16) float Bs[64][68];
    int tid = threadIdx.x;
    int p = blockIdx.z >> 3, kz = blockIdx.z & 7;
    const float* A = p ? A1 : A0;  int lda = p ? lda1 : lda0;
    const float* B = p ? B1 : B0;  int ldb = p ? ldb1 : ldb0;
    int n0 = blockIdx.x * 64, m0 = blockIdx.y * 64;
    int k0 = kz * 64;
    int tr = tid / 16, tc = tid % 16;      // 8 x 16 thread grid
    int lr = tid / 16, lc4 = (tid % 16) * 4;

    #pragma unroll
    for (int h = 0; h < 8; h++) {
        int r = lr + h * 8;
        float4 a = *(const float4*)(A + (size_t)(m0 + r) * lda + k0 + lc4);
        As[lc4 + 0][r] = a.x; As[lc4 + 1][r] = a.y;
        As[lc4 + 2][r] = a.z; As[lc4 + 3][r] = a.w;
        *(float4*)&Bs[r][lc4] = *(const float4*)(B + (size_t)(k0 + r) * ldb + n0 + lc4);
    }
    __syncthreads();

    float acc[8][4];
    #pragma unroll
    for (int i = 0; i < 8; i++)
        #pragma unroll
        for (int j = 0; j < 4; j++) acc[i][j] = 0.f;

    #pragma unroll 4
    for (int k = 0; k < 64; k++) {
        float a[8];
        *(float4*)&a[0] = *(const float4*)&As[k][tr * 8];
        *(float4*)&a[4] = *(const float4*)&As[k][tr * 8 + 4];
        float4 rb = *(const float4*)&Bs[k][tc * 4];
        float b[4] = {rb.x, rb.y, rb.z, rb.w};
        #pragma unroll
        for (int i = 0; i < 8; i++)
            #pragma unroll
            for (int j = 0; j < 4; j++)
                acc[i][j] += a[i] * b[j];
    }

    float* part = g_PART + (size_t)blockIdx.z * CC * CC;
    #pragma unroll
    for (int i = 0; i < 8; i++)
        *(float4*)(part + (size_t)(m0 + tr * 8 + i) * CC + n0 + tc * 4) =
            make_float4(acc[i][0], acc[i][1], acc[i][2], acc[i][3]);
}

__global__ void __launch_bounds__(256)
k_sred2(float* __restrict__ d0, int ldc0, float* __restrict__ d1, int ldc1) {
    int p = blockIdx.y;
    float* dst = p ? d1 : d0;
    int ldc = p ? ldc1 : ldc0;
    const float* base = g_PART + (size_t)p * 8 * CC * CC;
    int m = blockIdx.x;
    int n = threadIdx.x * 2;
    #pragma unroll
    for (int q = 0; q < 2; q++) {
        float s = 0.f;
        #pragma unroll
        for (int sl = 0; sl < 8; sl++)
            s += base[(size_t)sl * CC * CC + (size_t)m * CC + n + q];
        dst[(size_t)m * ldc + n + q] = s;
    }
}

// ---------------------------------------------------------------------------
// Bias folding
// ---------------------------------------------------------------------------
__global__ void k_bias1(const float* __restrict__ wp, const float* __restrict__ bp,
                        const float* __restrict__ wi, const float* __restrict__ bi,
                        const float* __restrict__ bo) {
    int i = threadIdx.x + blockIdx.x * 128;
    float s0 = bp[i], s1 = bi[i];
    for (int k = 0; k < CC; k++) {
        float b = bo[k];
        s0 += wp[i * CC + k] * b;
        s1 += wi[i * CC + k] * b;
    }
    g_BB[i] = s0;
    g_BB[CC + i] = s1;
}
__global__ void k_bias2(const float* __restrict__ w2, const float* __restrict__ b2) {
    int n = threadIdx.x + blockIdx.x * 128;
    float s = b2[n];
    for (int a = 0; a < CC; a++)
        s += w2[n * 2 * CC + a] * g_BB[a] + w2[n * 2 * CC + CC + a] * g_BB[CC + a];
    g_BT[n] = s;
}

// ---------------------------------------------------------------------------
// K1: x (B, C, 2, T) -> XE fp16 with device embedding
// ---------------------------------------------------------------------------
__global__ void k_embed(const float* __restrict__ x, const float* __restrict__ emb) {
    __shared__ float s[32][33];
    int t0 = blockIdx.x * 32;
    int c0 = blockIdx.y * 32;
    int bd = blockIdx.z;
    int b = bd >> 1, d = bd & 1;

    #pragma unroll
    for (int j = 0; j < 4; j++) {
        int c = c0 + threadIdx.y + j * 8;
        s[threadIdx.y + j * 8][threadIdx.x] =
            x[(((size_t)b * CC + c) * 2 + d) * CT + t0 + threadIdx.x];
    }
    __syncthreads();
    #pragma unroll
    for (int j = 0; j < 4; j++) {
        int t = t0 + threadIdx.y + j * 8;
        int c = c0 + threadIdx.x;
        float v = s[threadIdx.x][threadIdx.y + j * 8] + emb[d * CC + c];
        g_XE[((size_t)(b * CT + t) * 2 + d) * CC + c] = __float2half(v);
    }
}

// ---------------------------------------------------------------------------
// HMMA GEMM, single fp16 product, 3-stage cp.async pipeline.
// D[m][n] = bias[n] + sum_k A[m][k]*B[n][k]
// MODE 2: fp32 transposed (B, C, T).  MODE 3: fp16 row-major.
// ---------------------------------------------------------------------------
__device__ __forceinline__ void load_chunk(
    uint32_t sbase,
    const __half* __restrict__ A, int lda, int m0,
    const __half* __restrict__ Bh, int ldw, int n0, int kc, int tid)
{
    #pragma unroll
    for (int t = 0; t < 4; t++) {
        int id = tid + t * 256;
        int r = id >> 3, j = id & 7;
        uint32_t off = SW128((uint32_t)(r * 128 + j * 16));
        size_t ga = (size_t)(m0 + r) * lda + (size_t)kc * BK + j * 8;
        cp16(sbase + off, A + ga);
        size_t gb = (size_t)(n0 + r) * ldw + (size_t)kc * BK + j * 8;
        cp16(sbase + 16384 + off, Bh + gb);
    }
    cp_commit();
}

template <int MODE, int NCHUNK>
__global__ void __launch_bounds__(256, 2)
k_tgemm(const __half* __restrict__ A, int lda,
        const __half* __restrict__ Bh, int ldw,
        const float* __restrict__ bias,
        float* __restrict__ of, __half* __restrict__ oh, int ldc)
{
    extern __shared__ __align__(1024) char smem[];
    uint32_t sb = smem_u32(smem);
    int tid = threadIdx.x, lane = tid & 31, wid = tid >> 5;
    int m0 = blockIdx.y * BM, n0 = blockIdx.x * BN;
    int wm = (wid >> 2) * 64, wn = (wid & 3) * 32;

    float acc[4][4][4];
    #pragma unroll
    for (int a = 0; a < 4; a++)
        #pragma unroll
        for (int b = 0; b < 4; b++)
            #pragma unroll
            for (int c = 0; c < 4; c++) acc[a][b][c] = 0.f;

    uint32_t axor   = (uint32_t)(lane & 7) << 4;
    uint32_t arow   = (uint32_t)(wm + (lane & 15)) * 128;
    uint32_t achunk = (uint32_t)(lane >> 4) * 16;
    uint32_t brow   = (uint32_t)(wn + (lane & 7) + ((lane >> 4) << 3)) * 128;
    uint32_t bchunk = (uint32_t)((lane >> 3) & 1) * 16;

    load_chunk(sb,             A, lda, m0, Bh, ldw, n0, 0, tid);
    if (NCHUNK > 1) load_chunk(sb + STAGE,     A, lda, m0, Bh, ldw, n0, 1, tid);
    if (NCHUNK > 2) load_chunk(sb + 2 * STAGE, A, lda, m0, Bh, ldw, n0, 2, tid);

    for (int i = 0; i < NCHUNK; i++) {
        if (i + 2 < NCHUNK) cp_wait2();
        else if (i + 1 < NCHUNK) cp_wait1();
        else cp_wait0();
        __syncthreads();
        uint32_t st = sb + (uint32_t)(i % 3) * STAGE;

        #pragma unroll
        for (int ks = 0; ks < 4; ks++) {
            uint32_t act = ((uint32_t)(ks * 32) + achunk) ^ axor;
            uint32_t bct = ((uint32_t)(ks * 32) + bchunk) ^ axor;
            uint32_t ah[4][4], bh[2][4];
            #pragma unroll
            for (int mi = 0; mi < 4; mi++)
                ldsm4(ah[mi], st + arow + (uint32_t)mi * 2048 + act);
            #pragma unroll
            for (int nj = 0; nj < 2; nj++)
                ldsm4(bh[nj], st + 16384 + brow + (uint32_t)nj * 2048 + bct);
            #pragma unroll
            for (int mi = 0; mi < 4; mi++)
                #pragma unroll
                for (int ni = 0; ni < 4; ni++)
                    mma16816(acc[mi][ni], ah[mi], &bh[ni >> 1][(ni & 1) * 2]);
        }
        __syncthreads();
        if (i + 3 < NCHUNK)
            load_chunk(sb + (uint32_t)(i % 3) * STAGE,
                       A, lda, m0, Bh, ldw, n0, i + 3, tid);
    }

    // epilogue: frags -> padded smem (+bias) -> coalesced stores
    float* epi = (float*)smem;
    int g = lane >> 2, t2 = (lane & 3) * 2;
    #pragma unroll
    for (int mi = 0; mi < 4; mi++) {
        #pragma unroll
        for (int ni = 0; ni < 4; ni++) {
            int r = wm + mi * 16 + g;
            int c = wn + ni * 8 + t2;
            float b0 = bias[n0 + c], b1 = bias[n0 + c + 1];
            epi[r * 132 + c]           = acc[mi][ni][0] + b0;
            epi[r * 132 + c + 1]       = acc[mi][ni][1] + b1;
            epi[(r + 8) * 132 + c]     = acc[mi][ni][2] + b0;
            epi[(r + 8) * 132 + c + 1] = acc[mi][ni][3] + b1;
        }
    }
    __syncthreads();

    if (MODE == 2) {
        int b = m0 >> 11, tb = m0 & (CT - 1);
        #pragma unroll 4
        for (int idx = tid; idx < BM * BN; idx += 256) {
            int n = idx >> 7, tt = idx & 127;
            of[(size_t)b * (CC * CT) + (size_t)(n0 + n) * CT + tb + tt] = epi[tt * 132 + n];
        }
    } else {  // MODE 3: fp16 row-major, half2 stores
        #pragma unroll 4
        for (int idx = tid; idx < BM * BN / 2; idx += 256) {
            int r = idx / (BN / 2), c = (idx % (BN / 2)) * 2;
            __half2 v = __floats2half2_rn(epi[r * 132 + c], epi[r * 132 + c + 1]);
            *(__half2*)(oh + (size_t)(m0 + r) * ldc + n0 + c) = v;
        }
    }
}

// ---------------------------------------------------------------------------
// K3: tiny 2x2 attention (fp16 QKV in); CTX fp16 + per-token head-avg probs.
// ---------------------------------------------------------------------------
__global__ void k_attn() {
    __shared__ float sp[2][CH][4];
    int tid = threadIdx.x;
    int local = tid >> 7;
    int token = blockIdx.x * 2 + local;
    int head = (tid >> 5) & 3;
    int lane = tid & 31;

    const __half* base0 = g_QKV + (size_t)(2 * token) * (3 * CC);
    const __half* base1 = base0 + 3 * CC;
    int col4 = head * CDH + lane * 4;

    float4 q0 = ld_half4(base0 + col4);
    float4 k0 = ld_half4(base0 + CC + col4);
    float4 v0 = ld_half4(base0 + 2 * CC + col4);
    float4 q1 = ld_half4(base1 + col4);
    float4 k1 = ld_half4(base1 + CC + col4);
    float4 v1 = ld_half4(base1 + 2 * CC + col4);

    float s00 = q0.x * k0.x + q0.y * k0.y + q0.z * k0.z + q0.w * k0.w;
    float s01 = q0.x * k1.x + q0.y * k1.y + q0.z * k1.z + q0.w * k1.w;
    float s10 = q1.x * k0.x + q1.y * k0.y + q1.z * k0.z + q1.w * k0.w;
    float s11 = q1.x * k1.x + q1.y * k1.y + q1.z * k1.z + q1.w * k1.w;

    #pragma unroll
    for (int o = 16; o > 0; o >>= 1) {
        s00 += __shfl_xor_sync(0xffffffffu, s00, o);
        s01 += __shfl_xor_sync(0xffffffffu, s01, o);
        s10 += __shfl_xor_sync(0xffffffffu, s10, o);
        s11 += __shfl_xor_sync(0xffffffffu, s11, o);
    }
    const float sc = 0.088388347648318447f;  // 1/sqrt(128)
    s00 *= sc; s01 *= sc; s10 *= sc; s11 *= sc;

    float mx0 = fmaxf(s00, s01);
    float e00 = expf(s00 - mx0), e01 = expf(s01 - mx0);
    float inv0 = 1.f / (e00 + e01);
    float p00 = e00 * inv0, p01 = e01 * inv0;

    float mx1 = fmaxf(s10, s11);
    float e10 = expf(s10 - mx1), e11 = expf(s11 - mx1);
    float inv1 = 1.f / (e10 + e11);
    float p10 = e10 * inv1, p11 = e11 * inv1;

    size_t row0 = (size_t)(2 * token) * CC;
    __half2* d00 = (__half2*)(g_CTX + row0 + col4);
    __half2* d10 = (__half2*)(g_CTX + row0 + CC + col4);
    d00[0] = __floats2half2_rn(p00 * v0.x + p01 * v1.x, p00 * v0.y + p01 * v1.y);
    d00[1] = __floats2half2_rn(p00 * v0.z + p01 * v1.z, p00 * v0.w + p01 * v1.w);
    d10[0] = __floats2half2_rn(p10 * v0.x + p11 * v1.x, p10 * v0.y + p11 * v1.y);
    d10[1] = __floats2half2_rn(p10 * v0.z + p11 * v1.z, p10 * v0.w + p11 * v1.w);

    if (lane == 0) {
        sp[local][head][0] = p00; sp[local][head][1] = p01;
        sp[local][head][2] = p10; sp[local][head][3] = p11;
    }
    __syncthreads();
    if ((tid & 127) < 4) {
        int j = tid & 3;
        float s = (sp[local][0][j] + sp[local][1][j]) +
                  (sp[local][2][j] + sp[local][3][j]);
        g_PATT[(size_t)token * 4 + j] = s * 0.25f;
    }
}

// ---------------------------------------------------------------------------
// K7: avg_attention tail
// ---------------------------------------------------------------------------
__global__ void k_avg(float* __restrict__ out) {
    __shared__ float red[256];
    int b = blockIdx.x;
    for (int j = 0; j < 4; j++) {
        float s = 0.f;
        for (int t = threadIdx.x; t < CT; t += 256)
            s += g_PATT[((size_t)b * CT + t) * 4 + j];
        red[threadIdx.x] = s;
        __syncthreads();
        for (int w = 128; w > 0; w >>= 1) {
            if (threadIdx.x < w) red[threadIdx.x] += red[threadIdx.x + w];
            __syncthreads();
        }
        if (threadIdx.x == 0)
            out[(size_t)CB * CC * CT + b * 4 + j] = red[0] * (1.0f / CT);
        __syncthreads();
    }
}

// ---------------------------------------------------------------------------
// Host launcher (graph-capturable: kernel launches only)
// ---------------------------------------------------------------------------
extern "C" void kernel_launch(void* const* d_in, const int* in_sizes, int n_in,
                              void* d_out, int out_size) {
    const float* x   = (const float*)d_in[0];
    const float* emb = (const float*)d_in[1];
    const float* w1  = (const float*)d_in[2];
    const float* b1  = (const float*)d_in[3];
    const float* wo  = (const float*)d_in[4];
    const float* bo  = (const float*)d_in[5];
    const float* wp  = (const float*)d_in[6];
    const float* bp  = (const float*)d_in[7];
    const float* wim = (const float*)d_in[8];
    const float* bim = (const float*)d_in[9];
    const float* w2  = (const float*)d_in[10];
    const float* b2  = (const float*)d_in[11];
    float* out = (float*)d_out;

    __half *xe, *qkv, *ctx, *w1h, *w1l, *uh, *ul;
    float *s1, *s2, *u, *bt;
    cudaGetSymbolAddress((void**)&xe,  g_XE);
    cudaGetSymbolAddress((void**)&qkv, g_QKV);
    cudaGetSymbolAddress((void**)&ctx, g_CTX);
    cudaGetSymbolAddress((void**)&w1h, g_W1h); cudaGetSymbolAddress((void**)&w1l, g_W1l);
    cudaGetSymbolAddress((void**)&s1,  g_S1);  cudaGetSymbolAddress((void**)&s2,  g_S2);
    cudaGetSymbolAddress((void**)&u,   g_U);
    cudaGetSymbolAddress((void**)&uh,  g_Uh);  cudaGetSymbolAddress((void**)&ul,  g_Ul);
    cudaGetSymbolAddress((void**)&bt,  g_BT);

    cudaFuncSetAttribute(k_tgemm<3, 8>,  cudaFuncAttributeMaxDynamicSharedMemorySize, SMEM_G);
    cudaFuncSetAttribute(k_tgemm<2, 16>, cudaFuncAttributeMaxDynamicSharedMemorySize, SMEM_G);

    // --- weight preprocessing ---
    k_cvt<<<(3 * CC * CC + 255) / 256, 256>>>(w1, w1h, w1l, 3 * CC * CC);
    // stage 1: S1 = W2a @ Wp, S2 = W2b @ Wi
    k_snn2<<<dim3(8, 8, 16), 128>>>(w2, 2 * CC, wp, CC, w2 + CC, 2 * CC, wim, CC);
    k_sred2<<<dim3(CC, 2), 256>>>(s1, CC, s2, CC);
    // stage 2: U = [S1 @ Wo | S2 @ Wo]
    k_snn2<<<dim3(8, 8, 16), 128>>>(s1, CC, wo, CC, s2, CC, wo, CC);
    k_sred2<<<dim3(CC, 2), 256>>>(u, 2 * CC, u + CC, 2 * CC);
    k_cvt<<<(CC * 2 * CC + 255) / 256, 256>>>(u, uh, ul, CC * 2 * CC);
    k_bias1<<<4, 128>>>(wp, bp, wim, bim, bo);
    k_bias2<<<4, 128>>>(w2, b2);

    // --- main pipeline ---
    k_embed<<<dim3(CT / 32, CC / 32, CB * 2), dim3(32, 8)>>>(x, emb);

    // GEMM1: QKV (65536 x 1536, K=512), single-product, fp16 out
    k_tgemm<3, 8><<<dim3(3 * CC / BN, NROW / BM), 256, SMEM_G>>>(
        xe, CC, w1h, CC, b1, nullptr, qkv, 3 * CC);

    // attention -> ctx fp16 (contiguous (NTOK, 1024) view)
    k_attn<<<NTOK / 2, 256>>>();

    // Fused out_proj+phone/imu+output: (32768 x 512, K=1024),
    // single-product, transposed fp32 store
    k_tgemm<2, 16><<<dim3(CC / BN, NTOK / BM), 256, SMEM_G>>>(
        ctx, 2 * CC, uh, 2 * CC, bt, out, nullptr, 0);

    // avg_attention tail
    k_avg<<<CB, 256>>>(out);
}